// round 11
// baseline (speedup 1.0000x reference)
#include <cuda_runtime.h>
#include <math.h>

#define NMAX 50000
#define EMAX 800000
#define KD 128
#define SCAN_CH 1024

__device__ float g_h[(size_t)NMAX * KD];
__device__ float g_o0[(size_t)NMAX * KD];

// fragment-ordered split weights (hi/lo packed per float4)
__device__ float g_wfp0[32768];
__device__ float g_wf10[32768];
__device__ float g_wf20[32768];
__device__ float g_wfp1[32768];
__device__ float g_wf11[16384];
__device__ float g_wf21[16384];

// CSR scratch (built once per call, reused by both layers)
__device__ int  g_cnt[NMAX];
__device__ int  g_rowptr[NMAX + 1];
__device__ int  g_cursor[NMAX];
__device__ int  g_bsum[64];
__device__ int  g_boff[64];
__device__ int2 g_edata[EMAX];

// ---------------- tf32 helpers ----------------
__device__ __forceinline__ float tf32_rna(float x) {
    unsigned u;
    asm("cvt.rna.tf32.f32 %0, %1;" : "=r"(u) : "f"(x));
    return __uint_as_float(u);
}

__device__ __forceinline__ void mma8(float* d, float a0, float a1, float a2, float a3,
                                     float b0, float b1)
{
    asm("mma.sync.aligned.m16n8k8.row.col.f32.tf32.tf32.f32 "
        "{%0,%1,%2,%3}, {%4,%5,%6,%7}, {%8,%9}, {%0,%1,%2,%3};"
        : "+f"(d[0]), "+f"(d[1]), "+f"(d[2]), "+f"(d[3])
        : "r"(__float_as_uint(a0)), "r"(__float_as_uint(a1)),
          "r"(__float_as_uint(a2)), "r"(__float_as_uint(a3)),
          "r"(__float_as_uint(b0)), "r"(__float_as_uint(b1)));
}

// =====================================================================
// all 6 weight splits in ONE launch (blockIdx.y = job)
// =====================================================================
__global__ void split_w6(const float* __restrict__ w0, const float* __restrict__ w1,
                         const float* __restrict__ w2, const float* __restrict__ w3,
                         const float* __restrict__ w4, const float* __restrict__ w5,
                         float* o0, float* o1, float* o2, float* o3, float* o4, float* o5)
{
    int j = blockIdx.y;
    const float* W;
    float* WF;
    int total;
    switch (j) {
        case 0: W = w0; WF = o0; total = 8192; break;
        case 1: W = w1; WF = o1; total = 8192; break;
        case 2: W = w2; WF = o2; total = 8192; break;
        case 3: W = w3; WF = o3; total = 8192; break;
        case 4: W = w4; WF = o4; total = 4096; break;
        default: W = w5; WF = o5; total = 4096; break;
    }
    int idx = blockIdx.x * 256 + threadIdx.x;
    if (idx >= total) return;
    int lane = idx & 31, blk = idx >> 5;
    int q = blk & 15, nt = blk >> 4;
    int n = nt * 8 + (lane >> 2), k = q * 8 + (lane & 3);
    float v0 = W[n * 128 + k], v1 = W[n * 128 + k + 4];
    float h0 = tf32_rna(v0), h1 = tf32_rna(v1);
    reinterpret_cast<float4*>(WF)[idx] = make_float4(h0, h1, v0 - h0, v1 - h1);
}

// ===================== CSR build =====================
__global__ void zero_cnt(int* __restrict__ cnt, int n)
{
    int i = blockIdx.x * blockDim.x + threadIdx.x;
    if (i < n) cnt[i] = 0;
}

__global__ void hist_kernel(const int* __restrict__ dst, int* __restrict__ cnt, int E)
{
    int i = blockIdx.x * blockDim.x + threadIdx.x;
    int stride = gridDim.x * blockDim.x;
    for (; i < E; i += stride) atomicAdd(&cnt[dst[i]], 1);
}

__global__ void scan_reduce(const int* __restrict__ cnt, int* __restrict__ bsum, int n)
{
    __shared__ int wsum[8];
    const int tid = threadIdx.x, lane = tid & 31, wid = tid >> 5;
    int base = blockIdx.x * SCAN_CH + tid * 4;
    int s = 0;
    #pragma unroll
    for (int j = 0; j < 4; ++j) {
        int i = base + j;
        s += (i < n) ? cnt[i] : 0;
    }
    #pragma unroll
    for (int off = 16; off > 0; off >>= 1)
        s += __shfl_xor_sync(0xffffffffu, s, off);
    if (lane == 0) wsum[wid] = s;
    __syncthreads();
    if (tid == 0) {
        int t = 0;
        #pragma unroll
        for (int w = 0; w < 8; ++w) t += wsum[w];
        bsum[blockIdx.x] = t;
    }
}

__global__ void scan_blocks(const int* __restrict__ bsum, int* __restrict__ boff,
                            int* __restrict__ rowptr, int nb, int n)
{
    const int tid = threadIdx.x;   // 64 threads
    __shared__ int tmp[64];
    int v = (tid < nb) ? bsum[tid] : 0;
    tmp[tid] = v;
    __syncthreads();
    if (tid == 0) {
        int run = 0;
        for (int i = 0; i < nb; ++i) { int c = tmp[i]; tmp[i] = run; run += c; }
        rowptr[n] = run;
    }
    __syncthreads();
    if (tid < nb) boff[tid] = tmp[tid];
}

__global__ void scan_final(const int* __restrict__ cnt, const int* __restrict__ boff,
                           int* __restrict__ rowptr, int* __restrict__ cursor, int n)
{
    __shared__ int wsum[8];
    const int tid = threadIdx.x, lane = tid & 31, wid = tid >> 5;
    int base = blockIdx.x * SCAN_CH + tid * 4;
    int c[4];
    int tsum = 0;
    #pragma unroll
    for (int j = 0; j < 4; ++j) {
        int i = base + j;
        c[j] = (i < n) ? cnt[i] : 0;
        tsum += c[j];
    }
    int x = tsum;
    #pragma unroll
    for (int off = 1; off < 32; off <<= 1) {
        int t = __shfl_up_sync(0xffffffffu, x, off);
        if (lane >= off) x += t;
    }
    if (lane == 31) wsum[wid] = x;
    __syncthreads();
    if (wid == 0 && lane < 8) {
        int y = wsum[lane];
        #pragma unroll
        for (int off = 1; off < 8; off <<= 1) {
            int t = __shfl_up_sync(0xffu, y, off);
            if (lane >= off) y += t;
        }
        wsum[lane] = y;
    }
    __syncthreads();
    int run = x - tsum + (wid ? wsum[wid - 1] : 0) + boff[blockIdx.x];
    #pragma unroll
    for (int j = 0; j < 4; ++j) {
        int i = base + j;
        if (i < n) { rowptr[i] = run; cursor[i] = run; }
        run += c[j];
    }
}

__global__ void scatter_kernel(const int* __restrict__ src, const int* __restrict__ dst,
                               const float* __restrict__ val, int* __restrict__ cursor,
                               int2* __restrict__ edata, int E)
{
    int i = blockIdx.x * blockDim.x + threadIdx.x;
    int stride = gridDim.x * blockDim.x;
    for (; i < E; i += stride) {
        int d = dst[i];
        int pos = atomicAdd(&cursor[d], 1);
        edata[pos] = make_int2(src[i], __float_as_int(val[i]));
    }
}

// ---- stage A rows [64][128] into fragment layout (split hi/lo) ----
__device__ __forceinline__ void stage_a_split(const float* __restrict__ Ain,
                                              float* __restrict__ AH, float* __restrict__ AL,
                                              float* __restrict__ sumsq, bool do_sumsq,
                                              int tid, int m0, int n)
{
    float part = 0.f;
    int row = tid & 63;
    #pragma unroll
    for (int it = 0; it < 8; ++it) {
        int l = (tid >> 6) + it * 4;
        int m = m0 + row;
        float4 v = make_float4(0.f, 0.f, 0.f, 0.f);
        if (m < n) v = reinterpret_cast<const float4*>(Ain)[(size_t)m * 32 + l];
        if (do_sumsq)
            part += v.x * v.x + v.y * v.y + v.z * v.z + v.w * v.w;
        int t = row >> 4, r = row & 15;
        int q = l >> 1;
        int slot = (r >> 3) + ((l & 1) << 1);
        int base = (t * 16 + q) * 128 + ((r & 7) << 4) + slot;
        float vv[4] = {v.x, v.y, v.z, v.w};
        #pragma unroll
        for (int j = 0; j < 4; ++j) {
            float hi = tf32_rna(vv[j]);
            AH[base + j * 4] = hi;
            AL[base + j * 4] = vv[j] - hi;
        }
    }
    if (do_sumsq) atomicAdd(&sumsq[row], part);
}

// ---- gather-stage: compute agg rows m0..m0+63 from CSR, write sqrt to GR ----
// one warp per row iteration (warp w handles rows w, w+8, ..., w+56);
// lane owns float4 column = lane. Fragment mapping identical to stage_a (l = lane).
__device__ __forceinline__ void stage_gather(const float* __restrict__ Hm,
                                             const int2* __restrict__ edata,
                                             const int* __restrict__ rowptr,
                                             float* __restrict__ GR,
                                             int tid, int m0, int n)
{
    const int warp = tid >> 5, lane = tid & 31;
    const float4* H4 = reinterpret_cast<const float4*>(Hm);
    #pragma unroll
    for (int i = 0; i < 8; ++i) {
        int row = warp + i * 8;
        int m = m0 + row;
        float4 acc = make_float4(0.f, 0.f, 0.f, 0.f);
        if (m < n) {
            int e0 = __ldg(&rowptr[m]), e1 = __ldg(&rowptr[m + 1]);
            int e = e0;
            for (; e + 3 < e1; e += 4) {
                int2 ea = __ldg(&edata[e]);
                int2 eb = __ldg(&edata[e + 1]);
                int2 ec = __ldg(&edata[e + 2]);
                int2 ed = __ldg(&edata[e + 3]);
                float4 ha = __ldg(&H4[(size_t)ea.x * 32 + lane]);
                float4 hb = __ldg(&H4[(size_t)eb.x * 32 + lane]);
                float4 hc = __ldg(&H4[(size_t)ec.x * 32 + lane]);
                float4 hd = __ldg(&H4[(size_t)ed.x * 32 + lane]);
                float va = __int_as_float(ea.y), vb = __int_as_float(eb.y);
                float vc = __int_as_float(ec.y), vd = __int_as_float(ed.y);
                acc.x = fmaf(va * ha.x, ha.x, acc.x);
                acc.y = fmaf(va * ha.y, ha.y, acc.y);
                acc.z = fmaf(va * ha.z, ha.z, acc.z);
                acc.w = fmaf(va * ha.w, ha.w, acc.w);
                acc.x = fmaf(vb * hb.x, hb.x, acc.x);
                acc.y = fmaf(vb * hb.y, hb.y, acc.y);
                acc.z = fmaf(vb * hb.z, hb.z, acc.z);
                acc.w = fmaf(vb * hb.w, hb.w, acc.w);
                acc.x = fmaf(vc * hc.x, hc.x, acc.x);
                acc.y = fmaf(vc * hc.y, hc.y, acc.y);
                acc.z = fmaf(vc * hc.z, hc.z, acc.z);
                acc.w = fmaf(vc * hc.w, hc.w, acc.w);
                acc.x = fmaf(vd * hd.x, hd.x, acc.x);
                acc.y = fmaf(vd * hd.y, hd.y, acc.y);
                acc.z = fmaf(vd * hd.z, hd.z, acc.z);
                acc.w = fmaf(vd * hd.w, hd.w, acc.w);
            }
            for (; e < e1; ++e) {
                int2 ea = __ldg(&edata[e]);
                float va = __int_as_float(ea.y);
                float4 ha = __ldg(&H4[(size_t)ea.x * 32 + lane]);
                acc.x = fmaf(va * ha.x, ha.x, acc.x);
                acc.y = fmaf(va * ha.y, ha.y, acc.y);
                acc.z = fmaf(va * ha.z, ha.z, acc.z);
                acc.w = fmaf(va * ha.w, ha.w, acc.w);
            }
        }
        acc.x = sqrtf(acc.x); acc.y = sqrtf(acc.y);
        acc.z = sqrtf(acc.z); acc.w = sqrtf(acc.w);
        int t = row >> 4, r = row & 15;
        int q = lane >> 1;
        int slot = (r >> 3) + ((lane & 1) << 1);
        int base = (t * 16 + q) * 128 + ((r & 7) << 4) + slot;
        GR[base]      = acc.x;
        GR[base + 4]  = acc.y;
        GR[base + 8]  = acc.z;
        GR[base + 12] = acc.w;
    }
}

// =====================================================================
// pool GEMM + fused L2-norm + relu.
// =====================================================================
__global__ __launch_bounds__(256, 2)
void pool_gemm(const float* __restrict__ X, const float* __restrict__ WF,
               const float* __restrict__ B, float* __restrict__ H, int n)
{
    extern __shared__ float sm[];
    float* AH = sm;
    float* AL = AH + 8192;
    float* ss = AL + 8192;

    const int tid = threadIdx.x;
    const int warp = tid >> 5, lane = tid & 31;
    const int m0 = blockIdx.x * 64;

    if (tid < 64) ss[tid] = 0.f;
    __syncthreads();
    stage_a_split(X, AH, AL, ss, true, tid, m0, n);
    __syncthreads();

    const int wr = warp >> 2, wc = warp & 3;
    const float4* WF4 = reinterpret_cast<const float4*>(WF);

    float acc[2][4][4];
    #pragma unroll
    for (int a = 0; a < 2; ++a)
        #pragma unroll
        for (int b = 0; b < 4; ++b)
            #pragma unroll
            for (int c = 0; c < 4; ++c) acc[a][b][c] = 0.f;

    #pragma unroll 2
    for (int q = 0; q < 16; ++q) {
        float4 ah[2], al[2];
        #pragma unroll
        for (int mt = 0; mt < 2; ++mt) {
            int t = wr * 2 + mt;
            ah[mt] = *reinterpret_cast<const float4*>(&AH[(t * 16 + q) * 128 + lane * 4]);
            al[mt] = *reinterpret_cast<const float4*>(&AL[(t * 16 + q) * 128 + lane * 4]);
        }
        float4 wv[4];
        #pragma unroll
        for (int nl = 0; nl < 4; ++nl)
            wv[nl] = __ldg(&WF4[((wc * 4 + nl) * 16 + q) * 32 + lane]);

        #pragma unroll
        for (int mt = 0; mt < 2; ++mt)
            #pragma unroll
            for (int nl = 0; nl < 4; ++nl)
                mma8(acc[mt][nl], ah[mt].x, ah[mt].y, ah[mt].z, ah[mt].w, wv[nl].x, wv[nl].y);
        #pragma unroll
        for (int mt = 0; mt < 2; ++mt)
            #pragma unroll
            for (int nl = 0; nl < 4; ++nl)
                mma8(acc[mt][nl], al[mt].x, al[mt].y, al[mt].z, al[mt].w, wv[nl].x, wv[nl].y);
        #pragma unroll
        for (int mt = 0; mt < 2; ++mt)
            #pragma unroll
            for (int nl = 0; nl < 4; ++nl)
                mma8(acc[mt][nl], ah[mt].x, ah[mt].y, ah[mt].z, ah[mt].w, wv[nl].z, wv[nl].w);
    }

    #pragma unroll
    for (int mt = 0; mt < 2; ++mt) {
        #pragma unroll
        for (int rh = 0; rh < 2; ++rh) {
            int rloc = wr * 32 + mt * 16 + (lane >> 2) + rh * 8;
            int m = m0 + rloc;
            if (m >= n) continue;
            float inv = 1.0f / fmaxf(sqrtf(ss[rloc]), 1e-12f);
            #pragma unroll
            for (int nl = 0; nl < 4; ++nl) {
                int col = (wc * 4 + nl) * 8 + ((lane & 3) << 1);
                float2 r;
                r.x = fmaxf(fmaf(acc[mt][nl][rh * 2 + 0], inv, B[col]), 0.f);
                r.y = fmaxf(fmaf(acc[mt][nl][rh * 2 + 1], inv, B[col + 1]), 0.f);
                *reinterpret_cast<float2*>(&H[(size_t)m * 128 + col]) = r;
            }
        }
    }
}

// =====================================================================
// fused fc WITH INLINE SPMM:
//   GR rows gathered from CSR (agg = sum val*h^2, sqrt applied)
//   acc = H.W1^T + sqrt(agg).W2^T ; OUT = act(acc + B1 + B2)
// =====================================================================
template <int FOUT, bool RELU>
__global__ __launch_bounds__(256, 2)
void fc_gemm(const float* __restrict__ Hin,
             const int2* __restrict__ edata, const int* __restrict__ rowptr,
             const float* __restrict__ W1F, const float* __restrict__ W2F,
             const float* __restrict__ B1, const float* __restrict__ B2,
             float* __restrict__ OUT, int n)
{
    constexpr int NTW = FOUT / 32;
    extern __shared__ float sm[];
    float* AH = sm;
    float* AL = AH + 8192;
    float* GR = AL + 8192;

    const int tid = threadIdx.x;
    const int warp = tid >> 5, lane = tid & 31;
    const int m0 = blockIdx.x * 64;
    const int wr = warp >> 2, wc = warp & 3;

    stage_gather(Hin, edata, rowptr, GR, tid, m0, n);
    stage_a_split(Hin, AH, AL, nullptr, false, tid, m0, n);
    __syncthreads();

    const float4* W1_4 = reinterpret_cast<const float4*>(W1F);
    const float4* W2_4 = reinterpret_cast<const float4*>(W2F);

    float acc[2][NTW][4];
    #pragma unroll
    for (int a = 0; a < 2; ++a)
        #pragma unroll
        for (int b = 0; b < NTW; ++b)
            #pragma unroll
            for (int c = 0; c < 4; ++c) acc[a][b][c] = 0.f;

    #pragma unroll 2
    for (int q = 0; q < 16; ++q) {
        float4 ah[2], al[2], gh[2], gl[2];
        #pragma unroll
        for (int mt = 0; mt < 2; ++mt) {
            int t = wr * 2 + mt;
            int off = (t * 16 + q) * 128 + lane * 4;
            ah[mt] = *reinterpret_cast<const float4*>(&AH[off]);
            al[mt] = *reinterpret_cast<const float4*>(&AL[off]);
            float4 g = *reinterpret_cast<const float4*>(&GR[off]);
            gh[mt].x = tf32_rna(g.x); gh[mt].y = tf32_rna(g.y);
            gh[mt].z = tf32_rna(g.z); gh[mt].w = tf32_rna(g.w);
            gl[mt].x = g.x - gh[mt].x; gl[mt].y = g.y - gh[mt].y;
            gl[mt].z = g.z - gh[mt].z; gl[mt].w = g.w - gh[mt].w;
        }
        float4 w1[NTW], w2[NTW];
        #pragma unroll
        for (int nl = 0; nl < NTW; ++nl) {
            int fi = ((wc * NTW + nl) * 16 + q) * 32 + lane;
            w1[nl] = __ldg(&W1_4[fi]);
            w2[nl] = __ldg(&W2_4[fi]);
        }
        #pragma unroll
        for (int mt = 0; mt < 2; ++mt)
            #pragma unroll
            for (int nl = 0; nl < NTW; ++nl)
                mma8(acc[mt][nl], ah[mt].x, ah[mt].y, ah[mt].z, ah[mt].w, w1[nl].x, w1[nl].y);
        #pragma unroll
        for (int mt = 0; mt < 2; ++mt)
            #pragma unroll
            for (int nl = 0; nl < NTW; ++nl)
                mma8(acc[mt][nl], gh[mt].x, gh[mt].y, gh[mt].z, gh[mt].w, w2[nl].x, w2[nl].y);
        #pragma unroll
        for (int mt = 0; mt < 2; ++mt)
            #pragma unroll
            for (int nl = 0; nl < NTW; ++nl)
                mma8(acc[mt][nl], al[mt].x, al[mt].y, al[mt].z, al[mt].w, w1[nl].x, w1[nl].y);
        #pragma unroll
        for (int mt = 0; mt < 2; ++mt)
            #pragma unroll
            for (int nl = 0; nl < NTW; ++nl)
                mma8(acc[mt][nl], gl[mt].x, gl[mt].y, gl[mt].z, gl[mt].w, w2[nl].x, w2[nl].y);
        #pragma unroll
        for (int mt = 0; mt < 2; ++mt)
            #pragma unroll
            for (int nl = 0; nl < NTW; ++nl)
                mma8(acc[mt][nl], ah[mt].x, ah[mt].y, ah[mt].z, ah[mt].w, w1[nl].z, w1[nl].w);
        #pragma unroll
        for (int mt = 0; mt < 2; ++mt)
            #pragma unroll
            for (int nl = 0; nl < NTW; ++nl)
                mma8(acc[mt][nl], gh[mt].x, gh[mt].y, gh[mt].z, gh[mt].w, w2[nl].z, w2[nl].w);
    }

    #pragma unroll
    for (int mt = 0; mt < 2; ++mt) {
        #pragma unroll
        for (int rh = 0; rh < 2; ++rh) {
            int rloc = wr * 32 + mt * 16 + (lane >> 2) + rh * 8;
            int m = m0 + rloc;
            if (m >= n) continue;
            #pragma unroll
            for (int nl = 0; nl < NTW; ++nl) {
                int col = (wc * NTW + nl) * 8 + ((lane & 3) << 1);
                float2 r;
                r.x = acc[mt][nl][rh * 2 + 0] + B1[col] + B2[col];
                r.y = acc[mt][nl][rh * 2 + 1] + B1[col + 1] + B2[col + 1];
                if (RELU) { r.x = fmaxf(r.x, 0.f); r.y = fmaxf(r.y, 0.f); }
                *reinterpret_cast<float2*>(&OUT[(size_t)m * FOUT + col]) = r;
            }
        }
    }
}

// =====================================================================
extern "C" void kernel_launch(void* const* d_in, const int* in_sizes, int n_in,
                              void* d_out, int out_size)
{
    const float* x     = (const float*)d_in[0];
    const int*   esrc  = (const int*)  d_in[1];
    const int*   edst  = (const int*)  d_in[2];
    const float* eval_ = (const float*)d_in[3];
    const float* pw0   = (const float*)d_in[4];
    const float* pb0   = (const float*)d_in[5];
    const float* f1w0  = (const float*)d_in[6];
    const float* f1b0  = (const float*)d_in[7];
    const float* f2w0  = (const float*)d_in[8];
    const float* f2b0  = (const float*)d_in[9];
    const float* pw1   = (const float*)d_in[10];
    const float* pb1   = (const float*)d_in[11];
    const float* f1w1  = (const float*)d_in[12];
    const float* f1b1  = (const float*)d_in[13];
    const float* f2w1  = (const float*)d_in[14];
    const float* f2b1  = (const float*)d_in[15];
    float* out = (float*)d_out;

    int n = in_sizes[0] / KD;
    int E = in_sizes[1];

    float *hP, *oP;
    float *wp0, *w10, *w20, *wp1, *w11, *w21;
    int *cntP, *rpP, *curP, *bsP, *boP;
    int2 *edP;
    cudaGetSymbolAddress((void**)&hP, g_h);
    cudaGetSymbolAddress((void**)&oP, g_o0);
    cudaGetSymbolAddress((void**)&wp0, g_wfp0);
    cudaGetSymbolAddress((void**)&w10, g_wf10);
    cudaGetSymbolAddress((void**)&w20, g_wf20);
    cudaGetSymbolAddress((void**)&wp1, g_wfp1);
    cudaGetSymbolAddress((void**)&w11, g_wf11);
    cudaGetSymbolAddress((void**)&w21, g_wf21);
    cudaGetSymbolAddress((void**)&cntP, g_cnt);
    cudaGetSymbolAddress((void**)&rpP, g_rowptr);
    cudaGetSymbolAddress((void**)&curP, g_cursor);
    cudaGetSymbolAddress((void**)&bsP, g_bsum);
    cudaGetSymbolAddress((void**)&boP, g_boff);
    cudaGetSymbolAddress((void**)&edP, g_edata);

    const int POOL_SMEM = (8192 * 2 + 64) * 4;
    const int FC_SMEM   = (8192 * 3) * 4;
    cudaFuncSetAttribute(pool_gemm, cudaFuncAttributeMaxDynamicSharedMemorySize, POOL_SMEM);
    cudaFuncSetAttribute((const void*)fc_gemm<128, true>,
                         cudaFuncAttributeMaxDynamicSharedMemorySize, FC_SMEM);
    cudaFuncSetAttribute((const void*)fc_gemm<64, false>,
                         cudaFuncAttributeMaxDynamicSharedMemorySize, FC_SMEM);

    int mb = (n + 63) / 64;
    int nb = (n + SCAN_CH - 1) / SCAN_CH;    // <= 64

    // fork/join: CSR build on side stream, concurrent with split_w6 + pool0
    cudaStream_t s2;
    cudaStreamCreate(&s2);
    cudaEvent_t evFork, evJoin;
    cudaEventCreateWithFlags(&evFork, cudaEventDisableTiming);
    cudaEventCreateWithFlags(&evJoin, cudaEventDisableTiming);

    cudaEventRecord(evFork, 0);
    cudaStreamWaitEvent(s2, evFork, 0);

    // ---- side stream: CSR build ----
    zero_cnt<<<(n + 255) / 256, 256, 0, s2>>>(cntP, n);
    hist_kernel<<<512, 512, 0, s2>>>(edst, cntP, E);
    scan_reduce<<<nb, 256, 0, s2>>>(cntP, bsP, n);
    scan_blocks<<<1, 64, 0, s2>>>(bsP, boP, rpP, nb, n);
    scan_final<<<nb, 256, 0, s2>>>(cntP, boP, rpP, curP, n);
    scatter_kernel<<<512, 512, 0, s2>>>(esrc, edst, eval_, curP, edP, E);
    cudaEventRecord(evJoin, s2);

    // ---- main stream: weight splits + layer-0 pool ----
    split_w6<<<dim3(32, 6), 256>>>(pw0, f1w0, f2w0, pw1, f1w1, f2w1,
                                   wp0, w10, w20, wp1, w11, w21);
    pool_gemm<<<mb, 256, POOL_SMEM>>>(x, wp0, pb0, hP, n);

    // join: fused fc needs CSR (side) + hP (main)
    cudaStreamWaitEvent(0, evJoin, 0);

    fc_gemm<128, true><<<mb, 256, FC_SMEM>>>(hP, edP, rpP, w10, w20, f1b0, f2b0, oP, n);

    // ---- layer 1 ----
    pool_gemm<<<mb, 256, POOL_SMEM>>>(oP, wp1, pb1, hP, n);
    fc_gemm<64, false><<<mb, 256, FC_SMEM>>>(hP, edP, rpP, w11, w21, f1b1, f2b1, out, n);
}

// round 12
// speedup vs baseline: 1.1295x; 1.1295x over previous
#include <cuda_runtime.h>
#include <math.h>

#define NMAX 50000
#define EMAX 800000
#define KD 128
#define SCAN_CH 1024

__device__ float g_h[(size_t)NMAX * KD];
__device__ float g_agg[(size_t)NMAX * KD];
__device__ float g_o0[(size_t)NMAX * KD];

// fragment-ordered split weights (hi/lo packed per float4)
__device__ float g_wfp0[32768];
__device__ float g_wf10[32768];
__device__ float g_wf20[32768];
__device__ float g_wfp1[32768];
__device__ float g_wf11[16384];
__device__ float g_wf21[16384];

// CSR scratch
__device__ int  g_cnt[NMAX];
__device__ int  g_rowptr[NMAX + 1];
__device__ int  g_cursor[NMAX];
__device__ int  g_bsum[64];
__device__ int  g_boff[64];
__device__ int2 g_edata[EMAX];

// ---------------- tf32 helpers ----------------
__device__ __forceinline__ float tf32_rna(float x) {
    unsigned u;
    asm("cvt.rna.tf32.f32 %0, %1;" : "=r"(u) : "f"(x));
    return __uint_as_float(u);
}

__device__ __forceinline__ void mma8(float* d, float a0, float a1, float a2, float a3,
                                     float b0, float b1)
{
    asm("mma.sync.aligned.m16n8k8.row.col.f32.tf32.tf32.f32 "
        "{%0,%1,%2,%3}, {%4,%5,%6,%7}, {%8,%9}, {%0,%1,%2,%3};"
        : "+f"(d[0]), "+f"(d[1]), "+f"(d[2]), "+f"(d[3])
        : "r"(__float_as_uint(a0)), "r"(__float_as_uint(a1)),
          "r"(__float_as_uint(a2)), "r"(__float_as_uint(a3)),
          "r"(__float_as_uint(b0)), "r"(__float_as_uint(b1)));
}

// =====================================================================
// all 6 weight splits in ONE launch (blockIdx.y = job)
// =====================================================================
__global__ void split_w6(const float* __restrict__ w0, const float* __restrict__ w1,
                         const float* __restrict__ w2, const float* __restrict__ w3,
                         const float* __restrict__ w4, const float* __restrict__ w5,
                         float* o0, float* o1, float* o2, float* o3, float* o4, float* o5)
{
    int j = blockIdx.y;
    const float* W;
    float* WF;
    int total;
    switch (j) {
        case 0: W = w0; WF = o0; total = 8192; break;
        case 1: W = w1; WF = o1; total = 8192; break;
        case 2: W = w2; WF = o2; total = 8192; break;
        case 3: W = w3; WF = o3; total = 8192; break;
        case 4: W = w4; WF = o4; total = 4096; break;
        default: W = w5; WF = o5; total = 4096; break;
    }
    int idx = blockIdx.x * 256 + threadIdx.x;
    if (idx >= total) return;
    int lane = idx & 31, blk = idx >> 5;
    int q = blk & 15, nt = blk >> 4;
    int n = nt * 8 + (lane >> 2), k = q * 8 + (lane & 3);
    float v0 = W[n * 128 + k], v1 = W[n * 128 + k + 4];
    float h0 = tf32_rna(v0), h1 = tf32_rna(v1);
    reinterpret_cast<float4*>(WF)[idx] = make_float4(h0, h1, v0 - h0, v1 - h1);
}

// ===================== CSR build =====================
__global__ void zero_cnt(int* __restrict__ cnt, int n)
{
    int i = blockIdx.x * blockDim.x + threadIdx.x;
    if (i < n) cnt[i] = 0;
}

__global__ void hist_kernel(const int* __restrict__ dst, int* __restrict__ cnt, int E)
{
    int i = blockIdx.x * blockDim.x + threadIdx.x;
    int stride = gridDim.x * blockDim.x;
    for (; i < E; i += stride) atomicAdd(&cnt[dst[i]], 1);
}

__global__ void scan_reduce(const int* __restrict__ cnt, int* __restrict__ bsum, int n)
{
    __shared__ int wsum[8];
    const int tid = threadIdx.x, lane = tid & 31, wid = tid >> 5;
    int base = blockIdx.x * SCAN_CH + tid * 4;
    int s = 0;
    #pragma unroll
    for (int j = 0; j < 4; ++j) {
        int i = base + j;
        s += (i < n) ? cnt[i] : 0;
    }
    #pragma unroll
    for (int off = 16; off > 0; off >>= 1)
        s += __shfl_xor_sync(0xffffffffu, s, off);
    if (lane == 0) wsum[wid] = s;
    __syncthreads();
    if (tid == 0) {
        int t = 0;
        #pragma unroll
        for (int w = 0; w < 8; ++w) t += wsum[w];
        bsum[blockIdx.x] = t;
    }
}

__global__ void scan_blocks(const int* __restrict__ bsum, int* __restrict__ boff,
                            int* __restrict__ rowptr, int nb, int n)
{
    const int tid = threadIdx.x;   // 64 threads
    __shared__ int tmp[64];
    int v = (tid < nb) ? bsum[tid] : 0;
    tmp[tid] = v;
    __syncthreads();
    if (tid == 0) {
        int run = 0;
        for (int i = 0; i < nb; ++i) { int c = tmp[i]; tmp[i] = run; run += c; }
        rowptr[n] = run;
    }
    __syncthreads();
    if (tid < nb) boff[tid] = tmp[tid];
}

__global__ void scan_final(const int* __restrict__ cnt, const int* __restrict__ boff,
                           int* __restrict__ rowptr, int* __restrict__ cursor, int n)
{
    __shared__ int wsum[8];
    const int tid = threadIdx.x, lane = tid & 31, wid = tid >> 5;
    int base = blockIdx.x * SCAN_CH + tid * 4;
    int c[4];
    int tsum = 0;
    #pragma unroll
    for (int j = 0; j < 4; ++j) {
        int i = base + j;
        c[j] = (i < n) ? cnt[i] : 0;
        tsum += c[j];
    }
    int x = tsum;
    #pragma unroll
    for (int off = 1; off < 32; off <<= 1) {
        int t = __shfl_up_sync(0xffffffffu, x, off);
        if (lane >= off) x += t;
    }
    if (lane == 31) wsum[wid] = x;
    __syncthreads();
    if (wid == 0 && lane < 8) {
        int y = wsum[lane];
        #pragma unroll
        for (int off = 1; off < 8; off <<= 1) {
            int t = __shfl_up_sync(0xffu, y, off);
            if (lane >= off) y += t;
        }
        wsum[lane] = y;
    }
    __syncthreads();
    int run = x - tsum + (wid ? wsum[wid - 1] : 0) + boff[blockIdx.x];
    #pragma unroll
    for (int j = 0; j < 4; ++j) {
        int i = base + j;
        if (i < n) { rowptr[i] = run; cursor[i] = run; }
        run += c[j];
    }
}

__global__ void scatter_kernel(const int* __restrict__ src, const int* __restrict__ dst,
                               const float* __restrict__ val, int* __restrict__ cursor,
                               int2* __restrict__ edata, int E)
{
    int i = blockIdx.x * blockDim.x + threadIdx.x;
    int stride = gridDim.x * blockDim.x;
    for (; i < E; i += stride) {
        int d = dst[i];
        int pos = atomicAdd(&cursor[d], 1);
        edata[pos] = make_int2(src[i], __float_as_int(val[i]));
    }
}

// =====================================================================
// SpMM gather (standalone): AGG[r,:] = sum val*H[src,:]^2, warp/row
// =====================================================================
__global__ __launch_bounds__(256)
void spmm_gather(const int2* __restrict__ edata, const int* __restrict__ rowptr,
                 const float* __restrict__ Hm, float* __restrict__ AGG, int n)
{
    int gw = (int)((blockIdx.x * 256u + threadIdx.x) >> 5);
    int lane = threadIdx.x & 31;
    if (gw >= n) return;
    int e0 = rowptr[gw], e1 = rowptr[gw + 1];
    const float4* H4 = reinterpret_cast<const float4*>(Hm);
    float4 acc = make_float4(0.f, 0.f, 0.f, 0.f);
    int e = e0;
    for (; e + 3 < e1; e += 4) {
        int2 ea = __ldg(&edata[e]);
        int2 eb = __ldg(&edata[e + 1]);
        int2 ec = __ldg(&edata[e + 2]);
        int2 ed = __ldg(&edata[e + 3]);
        float4 ha = __ldg(&H4[(size_t)ea.x * 32 + lane]);
        float4 hb = __ldg(&H4[(size_t)eb.x * 32 + lane]);
        float4 hc = __ldg(&H4[(size_t)ec.x * 32 + lane]);
        float4 hd = __ldg(&H4[(size_t)ed.x * 32 + lane]);
        float va = __int_as_float(ea.y), vb = __int_as_float(eb.y);
        float vc = __int_as_float(ec.y), vd = __int_as_float(ed.y);
        acc.x = fmaf(va * ha.x, ha.x, acc.x);
        acc.y = fmaf(va * ha.y, ha.y, acc.y);
        acc.z = fmaf(va * ha.z, ha.z, acc.z);
        acc.w = fmaf(va * ha.w, ha.w, acc.w);
        acc.x = fmaf(vb * hb.x, hb.x, acc.x);
        acc.y = fmaf(vb * hb.y, hb.y, acc.y);
        acc.z = fmaf(vb * hb.z, hb.z, acc.z);
        acc.w = fmaf(vb * hb.w, hb.w, acc.w);
        acc.x = fmaf(vc * hc.x, hc.x, acc.x);
        acc.y = fmaf(vc * hc.y, hc.y, acc.y);
        acc.z = fmaf(vc * hc.z, hc.z, acc.z);
        acc.w = fmaf(vc * hc.w, hc.w, acc.w);
        acc.x = fmaf(vd * hd.x, hd.x, acc.x);
        acc.y = fmaf(vd * hd.y, hd.y, acc.y);
        acc.z = fmaf(vd * hd.z, hd.z, acc.z);
        acc.w = fmaf(vd * hd.w, hd.w, acc.w);
    }
    for (; e < e1; ++e) {
        int2 ea = __ldg(&edata[e]);
        float va = __int_as_float(ea.y);
        float4 ha = __ldg(&H4[(size_t)ea.x * 32 + lane]);
        acc.x = fmaf(va * ha.x, ha.x, acc.x);
        acc.y = fmaf(va * ha.y, ha.y, acc.y);
        acc.z = fmaf(va * ha.z, ha.z, acc.z);
        acc.w = fmaf(va * ha.w, ha.w, acc.w);
    }
    reinterpret_cast<float4*>(AGG)[(size_t)gw * 32 + lane] = acc;
}

// ---- stage A rows [64][128] into fragment layout ----
// SPLIT=1: hi->AH, lo->AL. SPLIT=0: raw (opt sqrt) -> AH.
// MODE: 0 raw, 1 sqrt, 2 raw + sumsq atomic
template <int SPLIT, int MODE>
__device__ __forceinline__ void stage_a(const float* __restrict__ Ain, float* __restrict__ AH,
                                        float* __restrict__ AL, float* __restrict__ sumsq,
                                        int tid, int m0, int n)
{
    float part = 0.f;
    int row = tid & 63;
    #pragma unroll
    for (int it = 0; it < 8; ++it) {
        int l = (tid >> 6) + it * 4;
        int m = m0 + row;
        float4 v = make_float4(0.f, 0.f, 0.f, 0.f);
        if (m < n) v = reinterpret_cast<const float4*>(Ain)[(size_t)m * 32 + l];
        if (MODE == 1) {
            v.x = sqrtf(v.x); v.y = sqrtf(v.y); v.z = sqrtf(v.z); v.w = sqrtf(v.w);
        }
        if (MODE == 2)
            part += v.x * v.x + v.y * v.y + v.z * v.z + v.w * v.w;
        int t = row >> 4, r = row & 15;
        int q = l >> 1;
        int slot = (r >> 3) + ((l & 1) << 1);
        int base = (t * 16 + q) * 128 + ((r & 7) << 4) + slot;
        float vv[4] = {v.x, v.y, v.z, v.w};
        #pragma unroll
        for (int j = 0; j < 4; ++j) {
            if (SPLIT) {
                float hi = tf32_rna(vv[j]);
                AH[base + j * 4] = hi;
                AL[base + j * 4] = vv[j] - hi;
            } else {
                AH[base + j * 4] = vv[j];
            }
        }
    }
    if (MODE == 2) atomicAdd(&sumsq[row], part);
}

// =====================================================================
// pool GEMM + fused L2-norm + relu.
// =====================================================================
__global__ __launch_bounds__(256, 2)
void pool_gemm(const float* __restrict__ X, const float* __restrict__ WF,
               const float* __restrict__ B, float* __restrict__ H, int n)
{
    extern __shared__ float sm[];
    float* AH = sm;
    float* AL = AH + 8192;
    float* ss = AL + 8192;

    const int tid = threadIdx.x;
    const int warp = tid >> 5, lane = tid & 31;
    const int m0 = blockIdx.x * 64;

    if (tid < 64) ss[tid] = 0.f;
    __syncthreads();
    stage_a<1, 2>(X, AH, AL, ss, tid, m0, n);
    __syncthreads();

    const int wr = warp >> 2, wc = warp & 3;
    const float4* WF4 = reinterpret_cast<const float4*>(WF);

    float acc[2][4][4];
    #pragma unroll
    for (int a = 0; a < 2; ++a)
        #pragma unroll
        for (int b = 0; b < 4; ++b)
            #pragma unroll
            for (int c = 0; c < 4; ++c) acc[a][b][c] = 0.f;

    #pragma unroll 2
    for (int q = 0; q < 16; ++q) {
        float4 ah[2], al[2];
        #pragma unroll
        for (int mt = 0; mt < 2; ++mt) {
            int t = wr * 2 + mt;
            ah[mt] = *reinterpret_cast<const float4*>(&AH[(t * 16 + q) * 128 + lane * 4]);
            al[mt] = *reinterpret_cast<const float4*>(&AL[(t * 16 + q) * 128 + lane * 4]);
        }
        float4 wv[4];
        #pragma unroll
        for (int nl = 0; nl < 4; ++nl)
            wv[nl] = __ldg(&WF4[((wc * 4 + nl) * 16 + q) * 32 + lane]);

        #pragma unroll
        for (int mt = 0; mt < 2; ++mt)
            #pragma unroll
            for (int nl = 0; nl < 4; ++nl)
                mma8(acc[mt][nl], ah[mt].x, ah[mt].y, ah[mt].z, ah[mt].w, wv[nl].x, wv[nl].y);
        #pragma unroll
        for (int mt = 0; mt < 2; ++mt)
            #pragma unroll
            for (int nl = 0; nl < 4; ++nl)
                mma8(acc[mt][nl], al[mt].x, al[mt].y, al[mt].z, al[mt].w, wv[nl].x, wv[nl].y);
        #pragma unroll
        for (int mt = 0; mt < 2; ++mt)
            #pragma unroll
            for (int nl = 0; nl < 4; ++nl)
                mma8(acc[mt][nl], ah[mt].x, ah[mt].y, ah[mt].z, ah[mt].w, wv[nl].z, wv[nl].w);
    }

    #pragma unroll
    for (int mt = 0; mt < 2; ++mt) {
        #pragma unroll
        for (int rh = 0; rh < 2; ++rh) {
            int rloc = wr * 32 + mt * 16 + (lane >> 2) + rh * 8;
            int m = m0 + rloc;
            if (m >= n) continue;
            float inv = 1.0f / fmaxf(sqrtf(ss[rloc]), 1e-12f);
            #pragma unroll
            for (int nl = 0; nl < 4; ++nl) {
                int col = (wc * 4 + nl) * 8 + ((lane & 3) << 1);
                float2 r;
                r.x = fmaxf(fmaf(acc[mt][nl][rh * 2 + 0], inv, B[col]), 0.f);
                r.y = fmaxf(fmaf(acc[mt][nl][rh * 2 + 1], inv, B[col + 1]), 0.f);
                *reinterpret_cast<float2*>(&H[(size_t)m * 128 + col]) = r;
            }
        }
    }
}

// =====================================================================
// fc_h: OUT = H . W1^T   (partial, no bias/relu) — overlaps with spmm
// =====================================================================
template <int FOUT>
__global__ __launch_bounds__(256, 2)
void fc_h(const float* __restrict__ Hin, const float* __restrict__ W1F,
          float* __restrict__ OUT, int n)
{
    constexpr int NTW = FOUT / 32;
    extern __shared__ float sm[];
    float* AH = sm;
    float* AL = AH + 8192;

    const int tid = threadIdx.x;
    const int warp = tid >> 5, lane = tid & 31;
    const int m0 = blockIdx.x * 64;
    const int wr = warp >> 2, wc = warp & 3;

    stage_a<1, 0>(Hin, AH, AL, nullptr, tid, m0, n);
    __syncthreads();

    const float4* W1_4 = reinterpret_cast<const float4*>(W1F);

    float acc[2][NTW][4];
    #pragma unroll
    for (int a = 0; a < 2; ++a)
        #pragma unroll
        for (int b = 0; b < NTW; ++b)
            #pragma unroll
            for (int c = 0; c < 4; ++c) acc[a][b][c] = 0.f;

    #pragma unroll 2
    for (int q = 0; q < 16; ++q) {
        float4 ah[2], al[2];
        #pragma unroll
        for (int mt = 0; mt < 2; ++mt) {
            int t = wr * 2 + mt;
            int off = (t * 16 + q) * 128 + lane * 4;
            ah[mt] = *reinterpret_cast<const float4*>(&AH[off]);
            al[mt] = *reinterpret_cast<const float4*>(&AL[off]);
        }
        float4 w1[NTW];
        #pragma unroll
        for (int nl = 0; nl < NTW; ++nl)
            w1[nl] = __ldg(&W1_4[((wc * NTW + nl) * 16 + q) * 32 + lane]);

        #pragma unroll
        for (int mt = 0; mt < 2; ++mt)
            #pragma unroll
            for (int nl = 0; nl < NTW; ++nl)
                mma8(acc[mt][nl], ah[mt].x, ah[mt].y, ah[mt].z, ah[mt].w, w1[nl].x, w1[nl].y);
        #pragma unroll
        for (int mt = 0; mt < 2; ++mt)
            #pragma unroll
            for (int nl = 0; nl < NTW; ++nl)
                mma8(acc[mt][nl], al[mt].x, al[mt].y, al[mt].z, al[mt].w, w1[nl].x, w1[nl].y);
        #pragma unroll
        for (int mt = 0; mt < 2; ++mt)
            #pragma unroll
            for (int nl = 0; nl < NTW; ++nl)
                mma8(acc[mt][nl], ah[mt].x, ah[mt].y, ah[mt].z, ah[mt].w, w1[nl].z, w1[nl].w);
    }

    #pragma unroll
    for (int mt = 0; mt < 2; ++mt) {
        #pragma unroll
        for (int rh = 0; rh < 2; ++rh) {
            int rloc = wr * 32 + mt * 16 + (lane >> 2) + rh * 8;
            int m = m0 + rloc;
            if (m >= n) continue;
            #pragma unroll
            for (int nl = 0; nl < NTW; ++nl) {
                int col = (wc * NTW + nl) * 8 + ((lane & 3) << 1);
                float2 r;
                r.x = acc[mt][nl][rh * 2 + 0];
                r.y = acc[mt][nl][rh * 2 + 1];
                *reinterpret_cast<float2*>(&OUT[(size_t)m * FOUT + col]) = r;
            }
        }
    }
}

// =====================================================================
// fc_g: OUT = act( OUT_partial + sqrt(G).W2^T + B1 + B2 )
// =====================================================================
template <int FOUT, bool RELU>
__global__ __launch_bounds__(256, 2)
void fc_g(const float* __restrict__ G, const float* __restrict__ W2F,
          const float* __restrict__ B1, const float* __restrict__ B2,
          float* __restrict__ OUT, int n)
{
    constexpr int NTW = FOUT / 32;
    extern __shared__ float sm[];
    float* GR = sm;                // 8192 floats

    const int tid = threadIdx.x;
    const int warp = tid >> 5, lane = tid & 31;
    const int m0 = blockIdx.x * 64;
    const int wr = warp >> 2, wc = warp & 3;

    stage_a<0, 1>(G, GR, nullptr, nullptr, tid, m0, n);
    __syncthreads();

    const float4* W2_4 = reinterpret_cast<const float4*>(W2F);

    float acc[2][NTW][4];
    #pragma unroll
    for (int a = 0; a < 2; ++a)
        #pragma unroll
        for (int b = 0; b < NTW; ++b)
            #pragma unroll
            for (int c = 0; c < 4; ++c) acc[a][b][c] = 0.f;

    #pragma unroll 2
    for (int q = 0; q < 16; ++q) {
        float4 gh[2], gl[2];
        #pragma unroll
        for (int mt = 0; mt < 2; ++mt) {
            int t = wr * 2 + mt;
            float4 g = *reinterpret_cast<const float4*>(&GR[(t * 16 + q) * 128 + lane * 4]);
            gh[mt].x = tf32_rna(g.x); gh[mt].y = tf32_rna(g.y);
            gh[mt].z = tf32_rna(g.z); gh[mt].w = tf32_rna(g.w);
            gl[mt].x = g.x - gh[mt].x; gl[mt].y = g.y - gh[mt].y;
            gl[mt].z = g.z - gh[mt].z; gl[mt].w = g.w - gh[mt].w;
        }
        float4 w2[NTW];
        #pragma unroll
        for (int nl = 0; nl < NTW; ++nl)
            w2[nl] = __ldg(&W2_4[((wc * NTW + nl) * 16 + q) * 32 + lane]);

        #pragma unroll
        for (int mt = 0; mt < 2; ++mt)
            #pragma unroll
            for (int nl = 0; nl < NTW; ++nl)
                mma8(acc[mt][nl], gh[mt].x, gh[mt].y, gh[mt].z, gh[mt].w, w2[nl].x, w2[nl].y);
        #pragma unroll
        for (int mt = 0; mt < 2; ++mt)
            #pragma unroll
            for (int nl = 0; nl < NTW; ++nl)
                mma8(acc[mt][nl], gl[mt].x, gl[mt].y, gl[mt].z, gl[mt].w, w2[nl].x, w2[nl].y);
        #pragma unroll
        for (int mt = 0; mt < 2; ++mt)
            #pragma unroll
            for (int nl = 0; nl < NTW; ++nl)
                mma8(acc[mt][nl], gh[mt].x, gh[mt].y, gh[mt].z, gh[mt].w, w2[nl].z, w2[nl].w);
    }

    #pragma unroll
    for (int mt = 0; mt < 2; ++mt) {
        #pragma unroll
        for (int rh = 0; rh < 2; ++rh) {
            int rloc = wr * 32 + mt * 16 + (lane >> 2) + rh * 8;
            int m = m0 + rloc;
            if (m >= n) continue;
            #pragma unroll
            for (int nl = 0; nl < NTW; ++nl) {
                int col = (wc * NTW + nl) * 8 + ((lane & 3) << 1);
                float2 o = *reinterpret_cast<const float2*>(&OUT[(size_t)m * FOUT + col]);
                float2 r;
                r.x = o.x + acc[mt][nl][rh * 2 + 0] + B1[col] + B2[col];
                r.y = o.y + acc[mt][nl][rh * 2 + 1] + B1[col + 1] + B2[col + 1];
                if (RELU) { r.x = fmaxf(r.x, 0.f); r.y = fmaxf(r.y, 0.f); }
                *reinterpret_cast<float2*>(&OUT[(size_t)m * FOUT + col]) = r;
            }
        }
    }
}

// =====================================================================
extern "C" void kernel_launch(void* const* d_in, const int* in_sizes, int n_in,
                              void* d_out, int out_size)
{
    const float* x     = (const float*)d_in[0];
    const int*   esrc  = (const int*)  d_in[1];
    const int*   edst  = (const int*)  d_in[2];
    const float* eval_ = (const float*)d_in[3];
    const float* pw0   = (const float*)d_in[4];
    const float* pb0   = (const float*)d_in[5];
    const float* f1w0  = (const float*)d_in[6];
    const float* f1b0  = (const float*)d_in[7];
    const float* f2w0  = (const float*)d_in[8];
    const float* f2b0  = (const float*)d_in[9];
    const float* pw1   = (const float*)d_in[10];
    const float* pb1   = (const float*)d_in[11];
    const float* f1w1  = (const float*)d_in[12];
    const float* f1b1  = (const float*)d_in[13];
    const float* f2w1  = (const float*)d_in[14];
    const float* f2b1  = (const float*)d_in[15];
    float* out = (float*)d_out;

    int n = in_sizes[0] / KD;
    int E = in_sizes[1];

    float *hP, *aP, *oP;
    float *wp0, *w10, *w20, *wp1, *w11, *w21;
    int *cntP, *rpP, *curP, *bsP, *boP;
    int2 *edP;
    cudaGetSymbolAddress((void**)&hP, g_h);
    cudaGetSymbolAddress((void**)&aP, g_agg);
    cudaGetSymbolAddress((void**)&oP, g_o0);
    cudaGetSymbolAddress((void**)&wp0, g_wfp0);
    cudaGetSymbolAddress((void**)&w10, g_wf10);
    cudaGetSymbolAddress((void**)&w20, g_wf20);
    cudaGetSymbolAddress((void**)&wp1, g_wfp1);
    cudaGetSymbolAddress((void**)&w11, g_wf11);
    cudaGetSymbolAddress((void**)&w21, g_wf21);
    cudaGetSymbolAddress((void**)&cntP, g_cnt);
    cudaGetSymbolAddress((void**)&rpP, g_rowptr);
    cudaGetSymbolAddress((void**)&curP, g_cursor);
    cudaGetSymbolAddress((void**)&bsP, g_bsum);
    cudaGetSymbolAddress((void**)&boP, g_boff);
    cudaGetSymbolAddress((void**)&edP, g_edata);

    const int POOL_SMEM = (8192 * 2 + 64) * 4;   // 65,792 B
    const int FCH_SMEM  = (8192 * 2) * 4;        // 65,536 B
    const int FCG_SMEM  = 8192 * 4;              // 32,768 B
    cudaFuncSetAttribute(pool_gemm, cudaFuncAttributeMaxDynamicSharedMemorySize, POOL_SMEM);
    cudaFuncSetAttribute((const void*)fc_h<128>, cudaFuncAttributeMaxDynamicSharedMemorySize, FCH_SMEM);
    cudaFuncSetAttribute((const void*)fc_h<64>,  cudaFuncAttributeMaxDynamicSharedMemorySize, FCH_SMEM);
    cudaFuncSetAttribute((const void*)fc_g<128, true>,  cudaFuncAttributeMaxDynamicSharedMemorySize, FCG_SMEM);
    cudaFuncSetAttribute((const void*)fc_g<64, false>,  cudaFuncAttributeMaxDynamicSharedMemorySize, FCG_SMEM);

    int mb = (n + 63) / 64;
    int gb = (n * 32 + 255) / 256;
    int nb = (n + SCAN_CH - 1) / SCAN_CH;

    cudaStream_t s2;
    cudaStreamCreate(&s2);
    cudaEvent_t evFork, evPool0, evSp0, evPool1, evSp1;
    cudaEventCreateWithFlags(&evFork, cudaEventDisableTiming);
    cudaEventCreateWithFlags(&evPool0, cudaEventDisableTiming);
    cudaEventCreateWithFlags(&evSp0, cudaEventDisableTiming);
    cudaEventCreateWithFlags(&evPool1, cudaEventDisableTiming);
    cudaEventCreateWithFlags(&evSp1, cudaEventDisableTiming);

    cudaEventRecord(evFork, 0);
    cudaStreamWaitEvent(s2, evFork, 0);

    // ---- side stream: CSR build ----
    zero_cnt<<<(n + 255) / 256, 256, 0, s2>>>(cntP, n);
    hist_kernel<<<512, 512, 0, s2>>>(edst, cntP, E);
    scan_reduce<<<nb, 256, 0, s2>>>(cntP, bsP, n);
    scan_blocks<<<1, 64, 0, s2>>>(bsP, boP, rpP, nb, n);
    scan_final<<<nb, 256, 0, s2>>>(cntP, boP, rpP, curP, n);
    scatter_kernel<<<512, 512, 0, s2>>>(esrc, edst, eval_, curP, edP, E);

    // ---- main: weight splits + layer-0 pool ----
    split_w6<<<dim3(32, 6), 256>>>(pw0, f1w0, f2w0, pw1, f1w1, f2w1,
                                   wp0, w10, w20, wp1, w11, w21);
    pool_gemm<<<mb, 256, POOL_SMEM>>>(x, wp0, pb0, hP, n);
    cudaEventRecord(evPool0, 0);

    // ---- layer 0: spmm (side) || fc_h (main), then fc_g (main) ----
    cudaStreamWaitEvent(s2, evPool0, 0);
    spmm_gather<<<gb, 256, 0, s2>>>(edP, rpP, hP, aP, n);
    cudaEventRecord(evSp0, s2);

    fc_h<128><<<mb, 256, FCH_SMEM>>>(hP, w10, oP, n);
    cudaStreamWaitEvent(0, evSp0, 0);
    fc_g<128, true><<<mb, 256, FCG_SMEM>>>(aP, w20, f1b0, f2b0, oP, n);

    // ---- layer 1 ----
    pool_gemm<<<mb, 256, POOL_SMEM>>>(oP, wp1, pb1, hP, n);
    cudaEventRecord(evPool1, 0);

    cudaStreamWaitEvent(s2, evPool1, 0);
    spmm_gather<<<gb, 256, 0, s2>>>(edP, rpP, hP, aP, n);
    cudaEventRecord(evSp1, s2);

    fc_h<64><<<mb, 256, FCH_SMEM>>>(hP, w11, out, n);
    cudaStreamWaitEvent(0, evSp1, 0);
    fc_g<64, false><<<mb, 256, FCG_SMEM>>>(aP, w21, f1b1, f2b1, out, n);
}

// round 13
// speedup vs baseline: 1.2839x; 1.1367x over previous
#include <cuda_runtime.h>
#include <math.h>

#define NMAX 50000
#define EMAX 800000
#define KD 128
#define SCAN_CH 1024

__device__ float g_h[(size_t)NMAX * KD];
__device__ float g_agg[(size_t)NMAX * KD];
__device__ float g_o0[(size_t)NMAX * KD];

// fragment-ordered split weights (hi/lo packed per float4)
__device__ float g_wfp0[32768];
__device__ float g_wf10[32768];
__device__ float g_wf20[32768];
__device__ float g_wfp1[32768];
__device__ float g_wf11[16384];
__device__ float g_wf21[16384];

// CSR scratch
__device__ int  g_cnt[NMAX];
__device__ int  g_rowptr[NMAX + 1];
__device__ int  g_cursor[NMAX];
__device__ int  g_bsum[64];
__device__ int  g_boff[64];
__device__ int2 g_edata[EMAX];

// ---------------- tf32 helpers ----------------
__device__ __forceinline__ float tf32_rna(float x) {
    unsigned u;
    asm("cvt.rna.tf32.f32 %0, %1;" : "=r"(u) : "f"(x));
    return __uint_as_float(u);
}

__device__ __forceinline__ void mma8(float* d, float a0, float a1, float a2, float a3,
                                     float b0, float b1)
{
    asm("mma.sync.aligned.m16n8k8.row.col.f32.tf32.tf32.f32 "
        "{%0,%1,%2,%3}, {%4,%5,%6,%7}, {%8,%9}, {%0,%1,%2,%3};"
        : "+f"(d[0]), "+f"(d[1]), "+f"(d[2]), "+f"(d[3])
        : "r"(__float_as_uint(a0)), "r"(__float_as_uint(a1)),
          "r"(__float_as_uint(a2)), "r"(__float_as_uint(a3)),
          "r"(__float_as_uint(b0)), "r"(__float_as_uint(b1)));
}

// smem unit swizzle: logical 16B-unit u -> physical u ^ ((u>>3)&3)
__device__ __forceinline__ int swz(int u) { return u ^ ((u >> 3) & 3); }

// =====================================================================
// all 6 weight splits in ONE launch (blockIdx.y = job)
// =====================================================================
__global__ void split_w6(const float* __restrict__ w0, const float* __restrict__ w1,
                         const float* __restrict__ w2, const float* __restrict__ w3,
                         const float* __restrict__ w4, const float* __restrict__ w5,
                         float* o0, float* o1, float* o2, float* o3, float* o4, float* o5)
{
    int j = blockIdx.y;
    const float* W;
    float* WF;
    int total;
    switch (j) {
        case 0: W = w0; WF = o0; total = 8192; break;
        case 1: W = w1; WF = o1; total = 8192; break;
        case 2: W = w2; WF = o2; total = 8192; break;
        case 3: W = w3; WF = o3; total = 8192; break;
        case 4: W = w4; WF = o4; total = 4096; break;
        default: W = w5; WF = o5; total = 4096; break;
    }
    int idx = blockIdx.x * 256 + threadIdx.x;
    if (idx >= total) return;
    int lane = idx & 31, blk = idx >> 5;
    int q = blk & 15, nt = blk >> 4;
    int n = nt * 8 + (lane >> 2), k = q * 8 + (lane & 3);
    float v0 = W[n * 128 + k], v1 = W[n * 128 + k + 4];
    float h0 = tf32_rna(v0), h1 = tf32_rna(v1);
    reinterpret_cast<float4*>(WF)[idx] = make_float4(h0, h1, v0 - h0, v1 - h1);
}

// ===================== CSR build =====================
__global__ void zero_cnt(int* __restrict__ cnt, int n)
{
    int i = blockIdx.x * blockDim.x + threadIdx.x;
    if (i < n) cnt[i] = 0;
}

__global__ void hist_kernel(const int* __restrict__ dst, int* __restrict__ cnt, int E)
{
    int i = blockIdx.x * blockDim.x + threadIdx.x;
    int stride = gridDim.x * blockDim.x;
    for (; i < E; i += stride) atomicAdd(&cnt[dst[i]], 1);
}

__global__ void scan_reduce(const int* __restrict__ cnt, int* __restrict__ bsum, int n)
{
    __shared__ int wsum[8];
    const int tid = threadIdx.x, lane = tid & 31, wid = tid >> 5;
    int base = blockIdx.x * SCAN_CH + tid * 4;
    int s = 0;
    #pragma unroll
    for (int j = 0; j < 4; ++j) {
        int i = base + j;
        s += (i < n) ? cnt[i] : 0;
    }
    #pragma unroll
    for (int off = 16; off > 0; off >>= 1)
        s += __shfl_xor_sync(0xffffffffu, s, off);
    if (lane == 0) wsum[wid] = s;
    __syncthreads();
    if (tid == 0) {
        int t = 0;
        #pragma unroll
        for (int w = 0; w < 8; ++w) t += wsum[w];
        bsum[blockIdx.x] = t;
    }
}

__global__ void scan_blocks(const int* __restrict__ bsum, int* __restrict__ boff,
                            int* __restrict__ rowptr, int nb, int n)
{
    const int tid = threadIdx.x;   // 64 threads
    __shared__ int tmp[64];
    int v = (tid < nb) ? bsum[tid] : 0;
    tmp[tid] = v;
    __syncthreads();
    if (tid == 0) {
        int run = 0;
        for (int i = 0; i < nb; ++i) { int c = tmp[i]; tmp[i] = run; run += c; }
        rowptr[n] = run;
    }
    __syncthreads();
    if (tid < nb) boff[tid] = tmp[tid];
}

__global__ void scan_final(const int* __restrict__ cnt, const int* __restrict__ boff,
                           int* __restrict__ rowptr, int* __restrict__ cursor, int n)
{
    __shared__ int wsum[8];
    const int tid = threadIdx.x, lane = tid & 31, wid = tid >> 5;
    int base = blockIdx.x * SCAN_CH + tid * 4;
    int c[4];
    int tsum = 0;
    #pragma unroll
    for (int j = 0; j < 4; ++j) {
        int i = base + j;
        c[j] = (i < n) ? cnt[i] : 0;
        tsum += c[j];
    }
    int x = tsum;
    #pragma unroll
    for (int off = 1; off < 32; off <<= 1) {
        int t = __shfl_up_sync(0xffffffffu, x, off);
        if (lane >= off) x += t;
    }
    if (lane == 31) wsum[wid] = x;
    __syncthreads();
    if (wid == 0 && lane < 8) {
        int y = wsum[lane];
        #pragma unroll
        for (int off = 1; off < 8; off <<= 1) {
            int t = __shfl_up_sync(0xffu, y, off);
            if (lane >= off) y += t;
        }
        wsum[lane] = y;
    }
    __syncthreads();
    int run = x - tsum + (wid ? wsum[wid - 1] : 0) + boff[blockIdx.x];
    #pragma unroll
    for (int j = 0; j < 4; ++j) {
        int i = base + j;
        if (i < n) { rowptr[i] = run; cursor[i] = run; }
        run += c[j];
    }
}

__global__ void scatter_kernel(const int* __restrict__ src, const int* __restrict__ dst,
                               const float* __restrict__ val, int* __restrict__ cursor,
                               int2* __restrict__ edata, int E)
{
    int i = blockIdx.x * blockDim.x + threadIdx.x;
    int stride = gridDim.x * blockDim.x;
    for (; i < E; i += stride) {
        int d = dst[i];
        int pos = atomicAdd(&cursor[d], 1);
        edata[pos] = make_int2(src[i], __float_as_int(val[i]));
    }
}

// =====================================================================
// SpMM gather (standalone): AGG[r,:] = sum val*H[src,:]^2, warp/row
// =====================================================================
__global__ __launch_bounds__(256)
void spmm_gather(const int2* __restrict__ edata, const int* __restrict__ rowptr,
                 const float* __restrict__ Hm, float* __restrict__ AGG, int n)
{
    int gw = (int)((blockIdx.x * 256u + threadIdx.x) >> 5);
    int lane = threadIdx.x & 31;
    if (gw >= n) return;
    int e0 = rowptr[gw], e1 = rowptr[gw + 1];
    const float4* H4 = reinterpret_cast<const float4*>(Hm);
    float4 acc = make_float4(0.f, 0.f, 0.f, 0.f);
    int e = e0;
    for (; e + 3 < e1; e += 4) {
        int2 ea = __ldg(&edata[e]);
        int2 eb = __ldg(&edata[e + 1]);
        int2 ec = __ldg(&edata[e + 2]);
        int2 ed = __ldg(&edata[e + 3]);
        float4 ha = __ldg(&H4[(size_t)ea.x * 32 + lane]);
        float4 hb = __ldg(&H4[(size_t)eb.x * 32 + lane]);
        float4 hc = __ldg(&H4[(size_t)ec.x * 32 + lane]);
        float4 hd = __ldg(&H4[(size_t)ed.x * 32 + lane]);
        float va = __int_as_float(ea.y), vb = __int_as_float(eb.y);
        float vc = __int_as_float(ec.y), vd = __int_as_float(ed.y);
        acc.x = fmaf(va * ha.x, ha.x, acc.x);
        acc.y = fmaf(va * ha.y, ha.y, acc.y);
        acc.z = fmaf(va * ha.z, ha.z, acc.z);
        acc.w = fmaf(va * ha.w, ha.w, acc.w);
        acc.x = fmaf(vb * hb.x, hb.x, acc.x);
        acc.y = fmaf(vb * hb.y, hb.y, acc.y);
        acc.z = fmaf(vb * hb.z, hb.z, acc.z);
        acc.w = fmaf(vb * hb.w, hb.w, acc.w);
        acc.x = fmaf(vc * hc.x, hc.x, acc.x);
        acc.y = fmaf(vc * hc.y, hc.y, acc.y);
        acc.z = fmaf(vc * hc.z, hc.z, acc.z);
        acc.w = fmaf(vc * hc.w, hc.w, acc.w);
        acc.x = fmaf(vd * hd.x, hd.x, acc.x);
        acc.y = fmaf(vd * hd.y, hd.y, acc.y);
        acc.z = fmaf(vd * hd.z, hd.z, acc.z);
        acc.w = fmaf(vd * hd.w, hd.w, acc.w);
    }
    for (; e < e1; ++e) {
        int2 ea = __ldg(&edata[e]);
        float va = __int_as_float(ea.y);
        float4 ha = __ldg(&H4[(size_t)ea.x * 32 + lane]);
        acc.x = fmaf(va * ha.x, ha.x, acc.x);
        acc.y = fmaf(va * ha.y, ha.y, acc.y);
        acc.z = fmaf(va * ha.z, ha.z, acc.z);
        acc.w = fmaf(va * ha.w, ha.w, acc.w);
    }
    reinterpret_cast<float4*>(AGG)[(size_t)gw * 32 + lane] = acc;
}

// ---- stage A rows [64][128] into fragment layout (unit-swizzled) ----
// SPLIT=1: hi->AH, lo->AL. SPLIT=0: raw (opt sqrt) -> AH.
// MODE: 0 raw, 1 sqrt, 2 raw + sumsq atomic
template <int SPLIT, int MODE>
__device__ __forceinline__ void stage_a(const float* __restrict__ Ain, float* __restrict__ AH,
                                        float* __restrict__ AL, float* __restrict__ sumsq,
                                        int tid, int m0, int n)
{
    float part = 0.f;
    int row = tid & 63;
    #pragma unroll
    for (int it = 0; it < 8; ++it) {
        int l = (tid >> 6) + it * 4;
        int m = m0 + row;
        float4 v = make_float4(0.f, 0.f, 0.f, 0.f);
        if (m < n) v = reinterpret_cast<const float4*>(Ain)[(size_t)m * 32 + l];
        if (MODE == 1) {
            v.x = sqrtf(v.x); v.y = sqrtf(v.y); v.z = sqrtf(v.z); v.w = sqrtf(v.w);
        }
        if (MODE == 2)
            part += v.x * v.x + v.y * v.y + v.z * v.z + v.w * v.w;
        int t = row >> 4, r = row & 15;
        int q = l >> 1;
        int slot = (r >> 3) + ((l & 1) << 1);
        int rowbase = (t * 16 + q) * 128;
        int u0 = (r & 7) << 2;
        float vv[4] = {v.x, v.y, v.z, v.w};
        #pragma unroll
        for (int j = 0; j < 4; ++j) {
            int addr = rowbase + (swz(u0 + j) << 2) + slot;
            if (SPLIT) {
                float hi = tf32_rna(vv[j]);
                AH[addr] = hi;
                AL[addr] = vv[j] - hi;
            } else {
                AH[addr] = vv[j];
            }
        }
    }
    if (MODE == 2) atomicAdd(&sumsq[row], part);
}

// =====================================================================
// pool GEMM + fused L2-norm + relu.
// =====================================================================
__global__ __launch_bounds__(256, 2)
void pool_gemm(const float* __restrict__ X, const float* __restrict__ WF,
               const float* __restrict__ B, float* __restrict__ H, int n)
{
    extern __shared__ float sm[];
    float* AH = sm;
    float* AL = AH + 8192;
    float* ss = AL + 8192;

    const int tid = threadIdx.x;
    const int warp = tid >> 5, lane = tid & 31;
    const int m0 = blockIdx.x * 64;

    if (tid < 64) ss[tid] = 0.f;
    __syncthreads();
    stage_a<1, 2>(X, AH, AL, ss, tid, m0, n);
    __syncthreads();

    const int wr = warp >> 2, wc = warp & 3;
    const int lsw = swz(lane) << 2;
    const float4* WF4 = reinterpret_cast<const float4*>(WF);

    float acc[2][4][4];
    #pragma unroll
    for (int a = 0; a < 2; ++a)
        #pragma unroll
        for (int b = 0; b < 4; ++b)
            #pragma unroll
            for (int c = 0; c < 4; ++c) acc[a][b][c] = 0.f;

    #pragma unroll 2
    for (int q = 0; q < 16; ++q) {
        float4 ah[2], al[2];
        #pragma unroll
        for (int mt = 0; mt < 2; ++mt) {
            int t = wr * 2 + mt;
            int off = (t * 16 + q) * 128 + lsw;
            ah[mt] = *reinterpret_cast<const float4*>(&AH[off]);
            al[mt] = *reinterpret_cast<const float4*>(&AL[off]);
        }
        float4 wv[4];
        #pragma unroll
        for (int nl = 0; nl < 4; ++nl)
            wv[nl] = __ldg(&WF4[((wc * 4 + nl) * 16 + q) * 32 + lane]);

        #pragma unroll
        for (int mt = 0; mt < 2; ++mt)
            #pragma unroll
            for (int nl = 0; nl < 4; ++nl)
                mma8(acc[mt][nl], ah[mt].x, ah[mt].y, ah[mt].z, ah[mt].w, wv[nl].x, wv[nl].y);
        #pragma unroll
        for (int mt = 0; mt < 2; ++mt)
            #pragma unroll
            for (int nl = 0; nl < 4; ++nl)
                mma8(acc[mt][nl], al[mt].x, al[mt].y, al[mt].z, al[mt].w, wv[nl].x, wv[nl].y);
        #pragma unroll
        for (int mt = 0; mt < 2; ++mt)
            #pragma unroll
            for (int nl = 0; nl < 4; ++nl)
                mma8(acc[mt][nl], ah[mt].x, ah[mt].y, ah[mt].z, ah[mt].w, wv[nl].z, wv[nl].w);
    }

    #pragma unroll
    for (int mt = 0; mt < 2; ++mt) {
        #pragma unroll
        for (int rh = 0; rh < 2; ++rh) {
            int rloc = wr * 32 + mt * 16 + (lane >> 2) + rh * 8;
            int m = m0 + rloc;
            if (m >= n) continue;
            float inv = 1.0f / fmaxf(sqrtf(ss[rloc]), 1e-12f);
            #pragma unroll
            for (int nl = 0; nl < 4; ++nl) {
                int col = (wc * 4 + nl) * 8 + ((lane & 3) << 1);
                float2 r;
                r.x = fmaxf(fmaf(acc[mt][nl][rh * 2 + 0], inv, B[col]), 0.f);
                r.y = fmaxf(fmaf(acc[mt][nl][rh * 2 + 1], inv, B[col + 1]), 0.f);
                *reinterpret_cast<float2*>(&H[(size_t)m * 128 + col]) = r;
            }
        }
    }
}

// =====================================================================
// fc_h: OUT = H . W1^T   (partial, no bias/relu) — overlaps with spmm
// =====================================================================
template <int FOUT>
__global__ __launch_bounds__(256, 2)
void fc_h(const float* __restrict__ Hin, const float* __restrict__ W1F,
          float* __restrict__ OUT, int n)
{
    constexpr int NTW = FOUT / 32;
    extern __shared__ float sm[];
    float* AH = sm;
    float* AL = AH + 8192;

    const int tid = threadIdx.x;
    const int warp = tid >> 5, lane = tid & 31;
    const int m0 = blockIdx.x * 64;
    const int wr = warp >> 2, wc = warp & 3;
    const int lsw = swz(lane) << 2;

    stage_a<1, 0>(Hin, AH, AL, nullptr, tid, m0, n);
    __syncthreads();

    const float4* W1_4 = reinterpret_cast<const float4*>(W1F);

    float acc[2][NTW][4];
    #pragma unroll
    for (int a = 0; a < 2; ++a)
        #pragma unroll
        for (int b = 0; b < NTW; ++b)
            #pragma unroll
            for (int c = 0; c < 4; ++c) acc[a][b][c] = 0.f;

    #pragma unroll 2
    for (int q = 0; q < 16; ++q) {
        float4 ah[2], al[2];
        #pragma unroll
        for (int mt = 0; mt < 2; ++mt) {
            int t = wr * 2 + mt;
            int off = (t * 16 + q) * 128 + lsw;
            ah[mt] = *reinterpret_cast<const float4*>(&AH[off]);
            al[mt] = *reinterpret_cast<const float4*>(&AL[off]);
        }
        float4 w1[NTW];
        #pragma unroll
        for (int nl = 0; nl < NTW; ++nl)
            w1[nl] = __ldg(&W1_4[((wc * NTW + nl) * 16 + q) * 32 + lane]);

        #pragma unroll
        for (int mt = 0; mt < 2; ++mt)
            #pragma unroll
            for (int nl = 0; nl < NTW; ++nl)
                mma8(acc[mt][nl], ah[mt].x, ah[mt].y, ah[mt].z, ah[mt].w, w1[nl].x, w1[nl].y);
        #pragma unroll
        for (int mt = 0; mt < 2; ++mt)
            #pragma unroll
            for (int nl = 0; nl < NTW; ++nl)
                mma8(acc[mt][nl], al[mt].x, al[mt].y, al[mt].z, al[mt].w, w1[nl].x, w1[nl].y);
        #pragma unroll
        for (int mt = 0; mt < 2; ++mt)
            #pragma unroll
            for (int nl = 0; nl < NTW; ++nl)
                mma8(acc[mt][nl], ah[mt].x, ah[mt].y, ah[mt].z, ah[mt].w, w1[nl].z, w1[nl].w);
    }

    #pragma unroll
    for (int mt = 0; mt < 2; ++mt) {
        #pragma unroll
        for (int rh = 0; rh < 2; ++rh) {
            int rloc = wr * 32 + mt * 16 + (lane >> 2) + rh * 8;
            int m = m0 + rloc;
            if (m >= n) continue;
            #pragma unroll
            for (int nl = 0; nl < NTW; ++nl) {
                int col = (wc * NTW + nl) * 8 + ((lane & 3) << 1);
                float2 r;
                r.x = acc[mt][nl][rh * 2 + 0];
                r.y = acc[mt][nl][rh * 2 + 1];
                *reinterpret_cast<float2*>(&OUT[(size_t)m * FOUT + col]) = r;
            }
        }
    }
}

// =====================================================================
// fc_g: OUT = act( OUT_partial + sqrt(G).W2^T + B1 + B2 )
// =====================================================================
template <int FOUT, bool RELU>
__global__ __launch_bounds__(256, 2)
void fc_g(const float* __restrict__ G, const float* __restrict__ W2F,
          const float* __restrict__ B1, const float* __restrict__ B2,
          float* __restrict__ OUT, int n)
{
    constexpr int NTW = FOUT / 32;
    extern __shared__ float sm[];
    float* GR = sm;                // 8192 floats

    const int tid = threadIdx.x;
    const int warp = tid >> 5, lane = tid & 31;
    const int m0 = blockIdx.x * 64;
    const int wr = warp >> 2, wc = warp & 3;
    const int lsw = swz(lane) << 2;

    stage_a<0, 1>(G, GR, nullptr, nullptr, tid, m0, n);
    __syncthreads();

    const float4* W2_4 = reinterpret_cast<const float4*>(W2F);

    float acc[2][NTW][4];
    #pragma unroll
    for (int a = 0; a < 2; ++a)
        #pragma unroll
        for (int b = 0; b < NTW; ++b)
            #pragma unroll
            for (int c = 0; c < 4; ++c) acc[a][b][c] = 0.f;

    #pragma unroll 2
    for (int q = 0; q < 16; ++q) {
        float4 gh[2], gl[2];
        #pragma unroll
        for (int mt = 0; mt < 2; ++mt) {
            int t = wr * 2 + mt;
            float4 g = *reinterpret_cast<const float4*>(&GR[(t * 16 + q) * 128 + lsw]);
            gh[mt].x = tf32_rna(g.x); gh[mt].y = tf32_rna(g.y);
            gh[mt].z = tf32_rna(g.z); gh[mt].w = tf32_rna(g.w);
            gl[mt].x = g.x - gh[mt].x; gl[mt].y = g.y - gh[mt].y;
            gl[mt].z = g.z - gh[mt].z; gl[mt].w = g.w - gh[mt].w;
        }
        float4 w2[NTW];
        #pragma unroll
        for (int nl = 0; nl < NTW; ++nl)
            w2[nl] = __ldg(&W2_4[((wc * NTW + nl) * 16 + q) * 32 + lane]);

        #pragma unroll
        for (int mt = 0; mt < 2; ++mt)
            #pragma unroll
            for (int nl = 0; nl < NTW; ++nl)
                mma8(acc[mt][nl], gh[mt].x, gh[mt].y, gh[mt].z, gh[mt].w, w2[nl].x, w2[nl].y);
        #pragma unroll
        for (int mt = 0; mt < 2; ++mt)
            #pragma unroll
            for (int nl = 0; nl < NTW; ++nl)
                mma8(acc[mt][nl], gl[mt].x, gl[mt].y, gl[mt].z, gl[mt].w, w2[nl].x, w2[nl].y);
        #pragma unroll
        for (int mt = 0; mt < 2; ++mt)
            #pragma unroll
            for (int nl = 0; nl < NTW; ++nl)
                mma8(acc[mt][nl], gh[mt].x, gh[mt].y, gh[mt].z, gh[mt].w, w2[nl].z, w2[nl].w);
    }

    #pragma unroll
    for (int mt = 0; mt < 2; ++mt) {
        #pragma unroll
        for (int rh = 0; rh < 2; ++rh) {
            int rloc = wr * 32 + mt * 16 + (lane >> 2) + rh * 8;
            int m = m0 + rloc;
            if (m >= n) continue;
            #pragma unroll
            for (int nl = 0; nl < NTW; ++nl) {
                int col = (wc * NTW + nl) * 8 + ((lane & 3) << 1);
                float2 o = *reinterpret_cast<const float2*>(&OUT[(size_t)m * FOUT + col]);
                float2 r;
                r.x = o.x + acc[mt][nl][rh * 2 + 0] + B1[col] + B2[col];
                r.y = o.y + acc[mt][nl][rh * 2 + 1] + B1[col + 1] + B2[col + 1];
                if (RELU) { r.x = fmaxf(r.x, 0.f); r.y = fmaxf(r.y, 0.f); }
                *reinterpret_cast<float2*>(&OUT[(size_t)m * FOUT + col]) = r;
            }
        }
    }
}

// =====================================================================
extern "C" void kernel_launch(void* const* d_in, const int* in_sizes, int n_in,
                              void* d_out, int out_size)
{
    const float* x     = (const float*)d_in[0];
    const int*   esrc  = (const int*)  d_in[1];
    const int*   edst  = (const int*)  d_in[2];
    const float* eval_ = (const float*)d_in[3];
    const float* pw0   = (const float*)d_in[4];
    const float* pb0   = (const float*)d_in[5];
    const float* f1w0  = (const float*)d_in[6];
    const float* f1b0  = (const float*)d_in[7];
    const float* f2w0  = (const float*)d_in[8];
    const float* f2b0  = (const float*)d_in[9];
    const float* pw1   = (const float*)d_in[10];
    const float* pb1   = (const float*)d_in[11];
    const float* f1w1  = (const float*)d_in[12];
    const float* f1b1  = (const float*)d_in[13];
    const float* f2w1  = (const float*)d_in[14];
    const float* f2b1  = (const float*)d_in[15];
    float* out = (float*)d_out;

    int n = in_sizes[0] / KD;
    int E = in_sizes[1];

    float *hP, *aP, *oP;
    float *wp0, *w10, *w20, *wp1, *w11, *w21;
    int *cntP, *rpP, *curP, *bsP, *boP;
    int2 *edP;
    cudaGetSymbolAddress((void**)&hP, g_h);
    cudaGetSymbolAddress((void**)&aP, g_agg);
    cudaGetSymbolAddress((void**)&oP, g_o0);
    cudaGetSymbolAddress((void**)&wp0, g_wfp0);
    cudaGetSymbolAddress((void**)&w10, g_wf10);
    cudaGetSymbolAddress((void**)&w20, g_wf20);
    cudaGetSymbolAddress((void**)&wp1, g_wfp1);
    cudaGetSymbolAddress((void**)&w11, g_wf11);
    cudaGetSymbolAddress((void**)&w21, g_wf21);
    cudaGetSymbolAddress((void**)&cntP, g_cnt);
    cudaGetSymbolAddress((void**)&rpP, g_rowptr);
    cudaGetSymbolAddress((void**)&curP, g_cursor);
    cudaGetSymbolAddress((void**)&bsP, g_bsum);
    cudaGetSymbolAddress((void**)&boP, g_boff);
    cudaGetSymbolAddress((void**)&edP, g_edata);

    const int POOL_SMEM = (8192 * 2 + 64) * 4;
    const int FCH_SMEM  = (8192 * 2) * 4;
    const int FCG_SMEM  = 8192 * 4;
    cudaFuncSetAttribute(pool_gemm, cudaFuncAttributeMaxDynamicSharedMemorySize, POOL_SMEM);
    cudaFuncSetAttribute((const void*)fc_h<128>, cudaFuncAttributeMaxDynamicSharedMemorySize, FCH_SMEM);
    cudaFuncSetAttribute((const void*)fc_h<64>,  cudaFuncAttributeMaxDynamicSharedMemorySize, FCH_SMEM);
    cudaFuncSetAttribute((const void*)fc_g<128, true>,  cudaFuncAttributeMaxDynamicSharedMemorySize, FCG_SMEM);
    cudaFuncSetAttribute((const void*)fc_g<64, false>,  cudaFuncAttributeMaxDynamicSharedMemorySize, FCG_SMEM);

    int mb = (n + 63) / 64;
    int gb = (n * 32 + 255) / 256;
    int nb = (n + SCAN_CH - 1) / SCAN_CH;

    cudaStream_t s2;
    cudaStreamCreate(&s2);
    cudaEvent_t evFork, evPool0, evSp0, evPool1, evSp1;
    cudaEventCreateWithFlags(&evFork, cudaEventDisableTiming);
    cudaEventCreateWithFlags(&evPool0, cudaEventDisableTiming);
    cudaEventCreateWithFlags(&evSp0, cudaEventDisableTiming);
    cudaEventCreateWithFlags(&evPool1, cudaEventDisableTiming);
    cudaEventCreateWithFlags(&evSp1, cudaEventDisableTiming);

    cudaEventRecord(evFork, 0);
    cudaStreamWaitEvent(s2, evFork, 0);

    // ---- side stream: CSR build ----
    zero_cnt<<<(n + 255) / 256, 256, 0, s2>>>(cntP, n);
    hist_kernel<<<512, 512, 0, s2>>>(edst, cntP, E);
    scan_reduce<<<nb, 256, 0, s2>>>(cntP, bsP, n);
    scan_blocks<<<1, 64, 0, s2>>>(bsP, boP, rpP, nb, n);
    scan_final<<<nb, 256, 0, s2>>>(cntP, boP, rpP, curP, n);
    scatter_kernel<<<512, 512, 0, s2>>>(esrc, edst, eval_, curP, edP, E);

    // ---- main: weight splits + layer-0 pool ----
    split_w6<<<dim3(32, 6), 256>>>(pw0, f1w0, f2w0, pw1, f1w1, f2w1,
                                   wp0, w10, w20, wp1, w11, w21);
    pool_gemm<<<mb, 256, POOL_SMEM>>>(x, wp0, pb0, hP, n);
    cudaEventRecord(evPool0, 0);

    // ---- layer 0: spmm (side) || fc_h (main), then fc_g (main) ----
    cudaStreamWaitEvent(s2, evPool0, 0);
    spmm_gather<<<gb, 256, 0, s2>>>(edP, rpP, hP, aP, n);
    cudaEventRecord(evSp0, s2);

    fc_h<128><<<mb, 256, FCH_SMEM>>>(hP, w10, oP, n);
    cudaStreamWaitEvent(0, evSp0, 0);
    fc_g<128, true><<<mb, 256, FCG_SMEM>>>(aP, w20, f1b0, f2b0, oP, n);

    // ---- layer 1 ----
    pool_gemm<<<mb, 256, POOL_SMEM>>>(oP, wp1, pb1, hP, n);
    cudaEventRecord(evPool1, 0);

    cudaStreamWaitEvent(s2, evPool1, 0);
    spmm_gather<<<gb, 256, 0, s2>>>(edP, rpP, hP, aP, n);
    cudaEventRecord(evSp1, s2);

    fc_h<64><<<mb, 256, FCH_SMEM>>>(hP, w11, out, n);
    cudaStreamWaitEvent(0, evSp1, 0);
    fc_g<64, false><<<mb, 256, FCG_SMEM>>>(aP, w21, f1b1, f2b1, out, n);
}

// round 14
// speedup vs baseline: 1.3447x; 1.0474x over previous
#include <cuda_runtime.h>
#include <math.h>

#define NMAX 50000
#define EMAX 800000
#define KD 128
#define SCAN_CH 1024

__device__ float g_h[(size_t)NMAX * KD];
__device__ float g_agg[(size_t)NMAX * KD];
__device__ float g_part[(size_t)NMAX * KD];

// fragment-ordered split weights (hi/lo packed per float4)
__device__ float g_wfp0[32768];
__device__ float g_wf10[32768];
__device__ float g_wf20[32768];
__device__ float g_wfp1[32768];
__device__ float g_wf11[16384];
__device__ float g_wf21[16384];

// CSR scratch
__device__ int  g_cnt[NMAX];
__device__ int  g_rowptr[NMAX + 1];
__device__ int  g_cursor[NMAX];
__device__ int  g_bsum[64];
__device__ int  g_boff[64];
__device__ int2 g_edata[EMAX];

// ---------------- tf32 helpers ----------------
__device__ __forceinline__ float tf32_rna(float x) {
    unsigned u;
    asm("cvt.rna.tf32.f32 %0, %1;" : "=r"(u) : "f"(x));
    return __uint_as_float(u);
}

__device__ __forceinline__ void mma8(float* d, float a0, float a1, float a2, float a3,
                                     float b0, float b1)
{
    asm("mma.sync.aligned.m16n8k8.row.col.f32.tf32.tf32.f32 "
        "{%0,%1,%2,%3}, {%4,%5,%6,%7}, {%8,%9}, {%0,%1,%2,%3};"
        : "+f"(d[0]), "+f"(d[1]), "+f"(d[2]), "+f"(d[3])
        : "r"(__float_as_uint(a0)), "r"(__float_as_uint(a1)),
          "r"(__float_as_uint(a2)), "r"(__float_as_uint(a3)),
          "r"(__float_as_uint(b0)), "r"(__float_as_uint(b1)));
}

// smem unit swizzle: logical 16B-unit u -> physical u ^ ((u>>3)&3)
__device__ __forceinline__ int swz(int u) { return u ^ ((u >> 3) & 3); }

// fragment address of scalar (row in 0..63, col in 0..127)
__device__ __forceinline__ int frag_addr(int row, int c) {
    int t = row >> 4, r = row & 15;
    int q = c >> 3;
    int slot = (r >> 3) + (((c >> 2) & 1) << 1);
    int u = ((r & 7) << 2) + (c & 3);
    return (t * 16 + q) * 128 + (swz(u) << 2) + slot;
}

// =====================================================================
// all 6 weight splits in ONE launch (blockIdx.y = job)
// =====================================================================
__global__ void split_w6(const float* __restrict__ w0, const float* __restrict__ w1,
                         const float* __restrict__ w2, const float* __restrict__ w3,
                         const float* __restrict__ w4, const float* __restrict__ w5,
                         float* o0, float* o1, float* o2, float* o3, float* o4, float* o5)
{
    int j = blockIdx.y;
    const float* W;
    float* WF;
    int total;
    switch (j) {
        case 0: W = w0; WF = o0; total = 8192; break;
        case 1: W = w1; WF = o1; total = 8192; break;
        case 2: W = w2; WF = o2; total = 8192; break;
        case 3: W = w3; WF = o3; total = 8192; break;
        case 4: W = w4; WF = o4; total = 4096; break;
        default: W = w5; WF = o5; total = 4096; break;
    }
    int idx = blockIdx.x * 256 + threadIdx.x;
    if (idx >= total) return;
    int lane = idx & 31, blk = idx >> 5;
    int q = blk & 15, nt = blk >> 4;
    int n = nt * 8 + (lane >> 2), k = q * 8 + (lane & 3);
    float v0 = W[n * 128 + k], v1 = W[n * 128 + k + 4];
    float h0 = tf32_rna(v0), h1 = tf32_rna(v1);
    reinterpret_cast<float4*>(WF)[idx] = make_float4(h0, h1, v0 - h0, v1 - h1);
}

// ===================== CSR build =====================
__global__ void zero_cnt(int* __restrict__ cnt, int n)
{
    int i = blockIdx.x * blockDim.x + threadIdx.x;
    if (i < n) cnt[i] = 0;
}

__global__ void hist_kernel(const int* __restrict__ dst, int* __restrict__ cnt, int E)
{
    int i = blockIdx.x * blockDim.x + threadIdx.x;
    int stride = gridDim.x * blockDim.x;
    for (; i < E; i += stride) atomicAdd(&cnt[dst[i]], 1);
}

__global__ void scan_reduce(const int* __restrict__ cnt, int* __restrict__ bsum, int n)
{
    __shared__ int wsum[8];
    const int tid = threadIdx.x, lane = tid & 31, wid = tid >> 5;
    int base = blockIdx.x * SCAN_CH + tid * 4;
    int s = 0;
    #pragma unroll
    for (int j = 0; j < 4; ++j) {
        int i = base + j;
        s += (i < n) ? cnt[i] : 0;
    }
    #pragma unroll
    for (int off = 16; off > 0; off >>= 1)
        s += __shfl_xor_sync(0xffffffffu, s, off);
    if (lane == 0) wsum[wid] = s;
    __syncthreads();
    if (tid == 0) {
        int t = 0;
        #pragma unroll
        for (int w = 0; w < 8; ++w) t += wsum[w];
        bsum[blockIdx.x] = t;
    }
}

__global__ void scan_blocks(const int* __restrict__ bsum, int* __restrict__ boff,
                            int* __restrict__ rowptr, int nb, int n)
{
    const int tid = threadIdx.x;   // 64 threads
    __shared__ int tmp[64];
    int v = (tid < nb) ? bsum[tid] : 0;
    tmp[tid] = v;
    __syncthreads();
    if (tid == 0) {
        int run = 0;
        for (int i = 0; i < nb; ++i) { int c = tmp[i]; tmp[i] = run; run += c; }
        rowptr[n] = run;
    }
    __syncthreads();
    if (tid < nb) boff[tid] = tmp[tid];
}

__global__ void scan_final(const int* __restrict__ cnt, const int* __restrict__ boff,
                           int* __restrict__ rowptr, int* __restrict__ cursor, int n)
{
    __shared__ int wsum[8];
    const int tid = threadIdx.x, lane = tid & 31, wid = tid >> 5;
    int base = blockIdx.x * SCAN_CH + tid * 4;
    int c[4];
    int tsum = 0;
    #pragma unroll
    for (int j = 0; j < 4; ++j) {
        int i = base + j;
        c[j] = (i < n) ? cnt[i] : 0;
        tsum += c[j];
    }
    int x = tsum;
    #pragma unroll
    for (int off = 1; off < 32; off <<= 1) {
        int t = __shfl_up_sync(0xffffffffu, x, off);
        if (lane >= off) x += t;
    }
    if (lane == 31) wsum[wid] = x;
    __syncthreads();
    if (wid == 0 && lane < 8) {
        int y = wsum[lane];
        #pragma unroll
        for (int off = 1; off < 8; off <<= 1) {
            int t = __shfl_up_sync(0xffu, y, off);
            if (lane >= off) y += t;
        }
        wsum[lane] = y;
    }
    __syncthreads();
    int run = x - tsum + (wid ? wsum[wid - 1] : 0) + boff[blockIdx.x];
    #pragma unroll
    for (int j = 0; j < 4; ++j) {
        int i = base + j;
        if (i < n) { rowptr[i] = run; cursor[i] = run; }
        run += c[j];
    }
}

__global__ void scatter_kernel(const int* __restrict__ src, const int* __restrict__ dst,
                               const float* __restrict__ val, int* __restrict__ cursor,
                               int2* __restrict__ edata, int E)
{
    int i = blockIdx.x * blockDim.x + threadIdx.x;
    int stride = gridDim.x * blockDim.x;
    for (; i < E; i += stride) {
        int d = dst[i];
        int pos = atomicAdd(&cursor[d], 1);
        edata[pos] = make_int2(src[i], __float_as_int(val[i]));
    }
}

// =====================================================================
// SpMM gather: AGG[r,:] = sum val*H[src,:]^2, warp/row
// =====================================================================
__global__ __launch_bounds__(256)
void spmm_gather(const int2* __restrict__ edata, const int* __restrict__ rowptr,
                 const float* __restrict__ Hm, float* __restrict__ AGG, int n)
{
    int gw = (int)((blockIdx.x * 256u + threadIdx.x) >> 5);
    int lane = threadIdx.x & 31;
    if (gw >= n) return;
    int e0 = rowptr[gw], e1 = rowptr[gw + 1];
    const float4* H4 = reinterpret_cast<const float4*>(Hm);
    float4 acc = make_float4(0.f, 0.f, 0.f, 0.f);
    int e = e0;
    for (; e + 3 < e1; e += 4) {
        int2 ea = __ldg(&edata[e]);
        int2 eb = __ldg(&edata[e + 1]);
        int2 ec = __ldg(&edata[e + 2]);
        int2 ed = __ldg(&edata[e + 3]);
        float4 ha = __ldg(&H4[(size_t)ea.x * 32 + lane]);
        float4 hb = __ldg(&H4[(size_t)eb.x * 32 + lane]);
        float4 hc = __ldg(&H4[(size_t)ec.x * 32 + lane]);
        float4 hd = __ldg(&H4[(size_t)ed.x * 32 + lane]);
        float va = __int_as_float(ea.y), vb = __int_as_float(eb.y);
        float vc = __int_as_float(ec.y), vd = __int_as_float(ed.y);
        acc.x = fmaf(va * ha.x, ha.x, acc.x);
        acc.y = fmaf(va * ha.y, ha.y, acc.y);
        acc.z = fmaf(va * ha.z, ha.z, acc.z);
        acc.w = fmaf(va * ha.w, ha.w, acc.w);
        acc.x = fmaf(vb * hb.x, hb.x, acc.x);
        acc.y = fmaf(vb * hb.y, hb.y, acc.y);
        acc.z = fmaf(vb * hb.z, hb.z, acc.z);
        acc.w = fmaf(vb * hb.w, hb.w, acc.w);
        acc.x = fmaf(vc * hc.x, hc.x, acc.x);
        acc.y = fmaf(vc * hc.y, hc.y, acc.y);
        acc.z = fmaf(vc * hc.z, hc.z, acc.z);
        acc.w = fmaf(vc * hc.w, hc.w, acc.w);
        acc.x = fmaf(vd * hd.x, hd.x, acc.x);
        acc.y = fmaf(vd * hd.y, hd.y, acc.y);
        acc.z = fmaf(vd * hd.z, hd.z, acc.z);
        acc.w = fmaf(vd * hd.w, hd.w, acc.w);
    }
    for (; e < e1; ++e) {
        int2 ea = __ldg(&edata[e]);
        float va = __int_as_float(ea.y);
        float4 ha = __ldg(&H4[(size_t)ea.x * 32 + lane]);
        acc.x = fmaf(va * ha.x, ha.x, acc.x);
        acc.y = fmaf(va * ha.y, ha.y, acc.y);
        acc.z = fmaf(va * ha.z, ha.z, acc.z);
        acc.w = fmaf(va * ha.w, ha.w, acc.w);
    }
    reinterpret_cast<float4*>(AGG)[(size_t)gw * 32 + lane] = acc;
}

// ---- stage A rows [64][128] into fragment layout (unit-swizzled) ----
template <int SPLIT, int MODE>
__device__ __forceinline__ void stage_a(const float* __restrict__ Ain, float* __restrict__ AH,
                                        float* __restrict__ AL, float* __restrict__ sumsq,
                                        int tid, int m0, int n)
{
    float part = 0.f;
    int row = tid & 63;
    #pragma unroll
    for (int it = 0; it < 8; ++it) {
        int l = (tid >> 6) + it * 4;
        int m = m0 + row;
        float4 v = make_float4(0.f, 0.f, 0.f, 0.f);
        if (m < n) v = reinterpret_cast<const float4*>(Ain)[(size_t)m * 32 + l];
        if (MODE == 1) {
            v.x = sqrtf(v.x); v.y = sqrtf(v.y); v.z = sqrtf(v.z); v.w = sqrtf(v.w);
        }
        if (MODE == 2)
            part += v.x * v.x + v.y * v.y + v.z * v.z + v.w * v.w;
        int t = row >> 4, r = row & 15;
        int q = l >> 1;
        int slot = (r >> 3) + ((l & 1) << 1);
        int rowbase = (t * 16 + q) * 128;
        int u0 = (r & 7) << 2;
        float vv[4] = {v.x, v.y, v.z, v.w};
        #pragma unroll
        for (int j = 0; j < 4; ++j) {
            int addr = rowbase + (swz(u0 + j) << 2) + slot;
            if (SPLIT) {
                float hi = tf32_rna(vv[j]);
                AH[addr] = hi;
                AL[addr] = vv[j] - hi;
            } else {
                AH[addr] = vv[j];
            }
        }
    }
    if (MODE == 2) atomicAdd(&sumsq[row], part);
}

// ---- pool mainloop + epilogue (shared by pool_gemm and fcg_pool) ----
__device__ __forceinline__ void pool_body(const float* __restrict__ AH,
                                          const float* __restrict__ AL,
                                          const float* __restrict__ ss,
                                          const float* __restrict__ WF,
                                          const float* __restrict__ B,
                                          float* __restrict__ H,
                                          int warp, int lane, int m0, int n)
{
    const int wr = warp >> 2, wc = warp & 3;
    const int lsw = swz(lane) << 2;
    const float4* WF4 = reinterpret_cast<const float4*>(WF);

    float acc[2][4][4];
    #pragma unroll
    for (int a = 0; a < 2; ++a)
        #pragma unroll
        for (int b = 0; b < 4; ++b)
            #pragma unroll
            for (int c = 0; c < 4; ++c) acc[a][b][c] = 0.f;

    #pragma unroll 2
    for (int q = 0; q < 16; ++q) {
        float4 ah[2], al[2];
        #pragma unroll
        for (int mt = 0; mt < 2; ++mt) {
            int t = wr * 2 + mt;
            int off = (t * 16 + q) * 128 + lsw;
            ah[mt] = *reinterpret_cast<const float4*>(&AH[off]);
            al[mt] = *reinterpret_cast<const float4*>(&AL[off]);
        }
        float4 wv[4];
        #pragma unroll
        for (int nl = 0; nl < 4; ++nl)
            wv[nl] = __ldg(&WF4[((wc * 4 + nl) * 16 + q) * 32 + lane]);

        #pragma unroll
        for (int mt = 0; mt < 2; ++mt)
            #pragma unroll
            for (int nl = 0; nl < 4; ++nl)
                mma8(acc[mt][nl], ah[mt].x, ah[mt].y, ah[mt].z, ah[mt].w, wv[nl].x, wv[nl].y);
        #pragma unroll
        for (int mt = 0; mt < 2; ++mt)
            #pragma unroll
            for (int nl = 0; nl < 4; ++nl)
                mma8(acc[mt][nl], al[mt].x, al[mt].y, al[mt].z, al[mt].w, wv[nl].x, wv[nl].y);
        #pragma unroll
        for (int mt = 0; mt < 2; ++mt)
            #pragma unroll
            for (int nl = 0; nl < 4; ++nl)
                mma8(acc[mt][nl], ah[mt].x, ah[mt].y, ah[mt].z, ah[mt].w, wv[nl].z, wv[nl].w);
    }

    #pragma unroll
    for (int mt = 0; mt < 2; ++mt) {
        #pragma unroll
        for (int rh = 0; rh < 2; ++rh) {
            int rloc = wr * 32 + mt * 16 + (lane >> 2) + rh * 8;
            int m = m0 + rloc;
            if (m >= n) continue;
            float inv = 1.0f / fmaxf(sqrtf(ss[rloc]), 1e-12f);
            #pragma unroll
            for (int nl = 0; nl < 4; ++nl) {
                int col = (wc * 4 + nl) * 8 + ((lane & 3) << 1);
                float2 r;
                r.x = fmaxf(fmaf(acc[mt][nl][rh * 2 + 0], inv, B[col]), 0.f);
                r.y = fmaxf(fmaf(acc[mt][nl][rh * 2 + 1], inv, B[col + 1]), 0.f);
                *reinterpret_cast<float2*>(&H[(size_t)m * 128 + col]) = r;
            }
        }
    }
}

// =====================================================================
// pool GEMM + fused L2-norm + relu (layer 0 entry)
// =====================================================================
__global__ __launch_bounds__(256, 2)
void pool_gemm(const float* __restrict__ X, const float* __restrict__ WF,
               const float* __restrict__ B, float* __restrict__ H, int n)
{
    extern __shared__ float sm[];
    float* AH = sm;
    float* AL = AH + 8192;
    float* ss = AL + 8192;

    const int tid = threadIdx.x;
    const int warp = tid >> 5, lane = tid & 31;
    const int m0 = blockIdx.x * 64;

    if (tid < 64) ss[tid] = 0.f;
    __syncthreads();
    stage_a<1, 2>(X, AH, AL, ss, tid, m0, n);
    __syncthreads();

    pool_body(AH, AL, ss, WF, B, H, warp, lane, m0, n);
}

// =====================================================================
// fc_h: OUT = H . W1^T   (partial, no bias/relu) — overlaps with spmm
// =====================================================================
template <int FOUT>
__global__ __launch_bounds__(256, 2)
void fc_h(const float* __restrict__ Hin, const float* __restrict__ W1F,
          float* __restrict__ OUT, int n)
{
    constexpr int NTW = FOUT / 32;
    extern __shared__ float sm[];
    float* AH = sm;
    float* AL = AH + 8192;

    const int tid = threadIdx.x;
    const int warp = tid >> 5, lane = tid & 31;
    const int m0 = blockIdx.x * 64;
    const int wr = warp >> 2, wc = warp & 3;
    const int lsw = swz(lane) << 2;

    stage_a<1, 0>(Hin, AH, AL, nullptr, tid, m0, n);
    __syncthreads();

    const float4* W1_4 = reinterpret_cast<const float4*>(W1F);

    float acc[2][NTW][4];
    #pragma unroll
    for (int a = 0; a < 2; ++a)
        #pragma unroll
        for (int b = 0; b < NTW; ++b)
            #pragma unroll
            for (int c = 0; c < 4; ++c) acc[a][b][c] = 0.f;

    #pragma unroll 2
    for (int q = 0; q < 16; ++q) {
        float4 ah[2], al[2];
        #pragma unroll
        for (int mt = 0; mt < 2; ++mt) {
            int t = wr * 2 + mt;
            int off = (t * 16 + q) * 128 + lsw;
            ah[mt] = *reinterpret_cast<const float4*>(&AH[off]);
            al[mt] = *reinterpret_cast<const float4*>(&AL[off]);
        }
        float4 w1[NTW];
        #pragma unroll
        for (int nl = 0; nl < NTW; ++nl)
            w1[nl] = __ldg(&W1_4[((wc * NTW + nl) * 16 + q) * 32 + lane]);

        #pragma unroll
        for (int mt = 0; mt < 2; ++mt)
            #pragma unroll
            for (int nl = 0; nl < NTW; ++nl)
                mma8(acc[mt][nl], ah[mt].x, ah[mt].y, ah[mt].z, ah[mt].w, w1[nl].x, w1[nl].y);
        #pragma unroll
        for (int mt = 0; mt < 2; ++mt)
            #pragma unroll
            for (int nl = 0; nl < NTW; ++nl)
                mma8(acc[mt][nl], al[mt].x, al[mt].y, al[mt].z, al[mt].w, w1[nl].x, w1[nl].y);
        #pragma unroll
        for (int mt = 0; mt < 2; ++mt)
            #pragma unroll
            for (int nl = 0; nl < NTW; ++nl)
                mma8(acc[mt][nl], ah[mt].x, ah[mt].y, ah[mt].z, ah[mt].w, w1[nl].z, w1[nl].w);
    }

    #pragma unroll
    for (int mt = 0; mt < 2; ++mt) {
        #pragma unroll
        for (int rh = 0; rh < 2; ++rh) {
            int rloc = wr * 32 + mt * 16 + (lane >> 2) + rh * 8;
            int m = m0 + rloc;
            if (m >= n) continue;
            #pragma unroll
            for (int nl = 0; nl < NTW; ++nl) {
                int col = (wc * NTW + nl) * 8 + ((lane & 3) << 1);
                float2 r;
                r.x = acc[mt][nl][rh * 2 + 0];
                r.y = acc[mt][nl][rh * 2 + 1];
                *reinterpret_cast<float2*>(&OUT[(size_t)m * FOUT + col]) = r;
            }
        }
    }
}

// =====================================================================
// fc_g (standalone, final layer): OUT = OUT_partial + sqrt(G).W2^T + biases
// =====================================================================
template <int FOUT, bool RELU>
__global__ __launch_bounds__(256, 2)
void fc_g(const float* __restrict__ G, const float* __restrict__ W2F,
          const float* __restrict__ B1, const float* __restrict__ B2,
          float* __restrict__ OUT, int n)
{
    constexpr int NTW = FOUT / 32;
    extern __shared__ float sm[];
    float* GR = sm;

    const int tid = threadIdx.x;
    const int warp = tid >> 5, lane = tid & 31;
    const int m0 = blockIdx.x * 64;
    const int wr = warp >> 2, wc = warp & 3;
    const int lsw = swz(lane) << 2;

    stage_a<0, 1>(G, GR, nullptr, nullptr, tid, m0, n);
    __syncthreads();

    const float4* W2_4 = reinterpret_cast<const float4*>(W2F);

    float acc[2][NTW][4];
    #pragma unroll
    for (int a = 0; a < 2; ++a)
        #pragma unroll
        for (int b = 0; b < NTW; ++b)
            #pragma unroll
            for (int c = 0; c < 4; ++c) acc[a][b][c] = 0.f;

    #pragma unroll 2
    for (int q = 0; q < 16; ++q) {
        float4 gh[2], gl[2];
        #pragma unroll
        for (int mt = 0; mt < 2; ++mt) {
            int t = wr * 2 + mt;
            float4 g = *reinterpret_cast<const float4*>(&GR[(t * 16 + q) * 128 + lsw]);
            gh[mt].x = tf32_rna(g.x); gh[mt].y = tf32_rna(g.y);
            gh[mt].z = tf32_rna(g.z); gh[mt].w = tf32_rna(g.w);
            gl[mt].x = g.x - gh[mt].x; gl[mt].y = g.y - gh[mt].y;
            gl[mt].z = g.z - gh[mt].z; gl[mt].w = g.w - gh[mt].w;
        }
        float4 w2[NTW];
        #pragma unroll
        for (int nl = 0; nl < NTW; ++nl)
            w2[nl] = __ldg(&W2_4[((wc * NTW + nl) * 16 + q) * 32 + lane]);

        #pragma unroll
        for (int mt = 0; mt < 2; ++mt)
            #pragma unroll
            for (int nl = 0; nl < NTW; ++nl)
                mma8(acc[mt][nl], gh[mt].x, gh[mt].y, gh[mt].z, gh[mt].w, w2[nl].x, w2[nl].y);
        #pragma unroll
        for (int mt = 0; mt < 2; ++mt)
            #pragma unroll
            for (int nl = 0; nl < NTW; ++nl)
                mma8(acc[mt][nl], gl[mt].x, gl[mt].y, gl[mt].z, gl[mt].w, w2[nl].x, w2[nl].y);
        #pragma unroll
        for (int mt = 0; mt < 2; ++mt)
            #pragma unroll
            for (int nl = 0; nl < NTW; ++nl)
                mma8(acc[mt][nl], gh[mt].x, gh[mt].y, gh[mt].z, gh[mt].w, w2[nl].z, w2[nl].w);
    }

    #pragma unroll
    for (int mt = 0; mt < 2; ++mt) {
        #pragma unroll
        for (int rh = 0; rh < 2; ++rh) {
            int rloc = wr * 32 + mt * 16 + (lane >> 2) + rh * 8;
            int m = m0 + rloc;
            if (m >= n) continue;
            #pragma unroll
            for (int nl = 0; nl < NTW; ++nl) {
                int col = (wc * NTW + nl) * 8 + ((lane & 3) << 1);
                float2 o = *reinterpret_cast<const float2*>(&OUT[(size_t)m * FOUT + col]);
                float2 r;
                r.x = o.x + acc[mt][nl][rh * 2 + 0] + B1[col] + B2[col];
                r.y = o.y + acc[mt][nl][rh * 2 + 1] + B1[col + 1] + B2[col + 1];
                if (RELU) { r.x = fmaxf(r.x, 0.f); r.y = fmaxf(r.y, 0.f); }
                *reinterpret_cast<float2*>(&OUT[(size_t)m * FOUT + col]) = r;
            }
        }
    }
}

// =====================================================================
// FUSED fc_g(layer0) + pool(layer1):
//   o = relu(PART + sqrt(G).W2^T + B1 + B2)          [in registers]
//   restage o (hi/lo) + row sumsq, then pool GEMM -> Hout
// =====================================================================
__global__ __launch_bounds__(256, 2)
void fcg_pool(const float* __restrict__ G, const float* __restrict__ W2F,
              const float* __restrict__ B1, const float* __restrict__ B2,
              const float* __restrict__ PART,
              const float* __restrict__ WPF, const float* __restrict__ PB,
              float* __restrict__ Hout, int n)
{
    extern __shared__ float sm[];
    float* AH = sm;            // 8192
    float* AL = AH + 8192;     // 8192
    float* GR = AL + 8192;     // 8192
    float* ss = GR + 8192;     // 64

    const int tid = threadIdx.x;
    const int warp = tid >> 5, lane = tid & 31;
    const int m0 = blockIdx.x * 64;
    const int wr = warp >> 2, wc = warp & 3;
    const int lsw = swz(lane) << 2;

    if (tid < 64) ss[tid] = 0.f;
    stage_a<0, 1>(G, GR, nullptr, nullptr, tid, m0, n);
    __syncthreads();

    const float4* W2_4 = reinterpret_cast<const float4*>(W2F);

    float acc[2][4][4];
    #pragma unroll
    for (int a = 0; a < 2; ++a)
        #pragma unroll
        for (int b = 0; b < 4; ++b)
            #pragma unroll
            for (int c = 0; c < 4; ++c) acc[a][b][c] = 0.f;

    #pragma unroll 2
    for (int q = 0; q < 16; ++q) {
        float4 gh[2], gl[2];
        #pragma unroll
        for (int mt = 0; mt < 2; ++mt) {
            int t = wr * 2 + mt;
            float4 g = *reinterpret_cast<const float4*>(&GR[(t * 16 + q) * 128 + lsw]);
            gh[mt].x = tf32_rna(g.x); gh[mt].y = tf32_rna(g.y);
            gh[mt].z = tf32_rna(g.z); gh[mt].w = tf32_rna(g.w);
            gl[mt].x = g.x - gh[mt].x; gl[mt].y = g.y - gh[mt].y;
            gl[mt].z = g.z - gh[mt].z; gl[mt].w = g.w - gh[mt].w;
        }
        float4 w2[4];
        #pragma unroll
        for (int nl = 0; nl < 4; ++nl)
            w2[nl] = __ldg(&W2_4[((wc * 4 + nl) * 16 + q) * 32 + lane]);

        #pragma unroll
        for (int mt = 0; mt < 2; ++mt)
            #pragma unroll
            for (int nl = 0; nl < 4; ++nl)
                mma8(acc[mt][nl], gh[mt].x, gh[mt].y, gh[mt].z, gh[mt].w, w2[nl].x, w2[nl].y);
        #pragma unroll
        for (int mt = 0; mt < 2; ++mt)
            #pragma unroll
            for (int nl = 0; nl < 4; ++nl)
                mma8(acc[mt][nl], gl[mt].x, gl[mt].y, gl[mt].z, gl[mt].w, w2[nl].x, w2[nl].y);
        #pragma unroll
        for (int mt = 0; mt < 2; ++mt)
            #pragma unroll
            for (int nl = 0; nl < 4; ++nl)
                mma8(acc[mt][nl], gh[mt].x, gh[mt].y, gh[mt].z, gh[mt].w, w2[nl].z, w2[nl].w);
    }

    // epilogue: o = relu(PART + acc + biases); sumsq; restage into AH/AL
    float bs[8];
    #pragma unroll
    for (int nl = 0; nl < 4; ++nl) {
        int col = (wc * 4 + nl) * 8 + ((lane & 3) << 1);
        bs[2 * nl]     = B1[col] + B2[col];
        bs[2 * nl + 1] = B1[col + 1] + B2[col + 1];
    }

    #pragma unroll
    for (int mt = 0; mt < 2; ++mt) {
        #pragma unroll
        for (int rh = 0; rh < 2; ++rh) {
            int rloc = wr * 32 + mt * 16 + (lane >> 2) + rh * 8;
            int m = m0 + rloc;
            float rsum = 0.f;
            #pragma unroll
            for (int nl = 0; nl < 4; ++nl) {
                int col = (wc * 4 + nl) * 8 + ((lane & 3) << 1);
                float2 o = make_float2(0.f, 0.f);
                if (m < n) {
                    float2 p = *reinterpret_cast<const float2*>(&PART[(size_t)m * 128 + col]);
                    o.x = fmaxf(p.x + acc[mt][nl][rh * 2 + 0] + bs[2 * nl], 0.f);
                    o.y = fmaxf(p.y + acc[mt][nl][rh * 2 + 1] + bs[2 * nl + 1], 0.f);
                }
                rsum += o.x * o.x + o.y * o.y;
                float hx = tf32_rna(o.x), hy = tf32_rna(o.y);
                int a0 = frag_addr(rloc, col);
                int a1 = frag_addr(rloc, col + 1);
                AH[a0] = hx;  AL[a0] = o.x - hx;
                AH[a1] = hy;  AL[a1] = o.y - hy;
            }
            rsum += __shfl_xor_sync(0xffffffffu, rsum, 1);
            rsum += __shfl_xor_sync(0xffffffffu, rsum, 2);
            if ((lane & 3) == 0) atomicAdd(&ss[rloc], rsum);
        }
    }
    __syncthreads();

    pool_body(AH, AL, ss, WPF, PB, Hout, warp, lane, m0, n);
}

// =====================================================================
extern "C" void kernel_launch(void* const* d_in, const int* in_sizes, int n_in,
                              void* d_out, int out_size)
{
    const float* x     = (const float*)d_in[0];
    const int*   esrc  = (const int*)  d_in[1];
    const int*   edst  = (const int*)  d_in[2];
    const float* eval_ = (const float*)d_in[3];
    const float* pw0   = (const float*)d_in[4];
    const float* pb0   = (const float*)d_in[5];
    const float* f1w0  = (const float*)d_in[6];
    const float* f1b0  = (const float*)d_in[7];
    const float* f2w0  = (const float*)d_in[8];
    const float* f2b0  = (const float*)d_in[9];
    const float* pw1   = (const float*)d_in[10];
    const float* pb1   = (const float*)d_in[11];
    const float* f1w1  = (const float*)d_in[12];
    const float* f1b1  = (const float*)d_in[13];
    const float* f2w1  = (const float*)d_in[14];
    const float* f2b1  = (const float*)d_in[15];
    float* out = (float*)d_out;

    int n = in_sizes[0] / KD;
    int E = in_sizes[1];

    float *hP, *aP, *pP;
    float *wp0, *w10, *w20, *wp1, *w11, *w21;
    int *cntP, *rpP, *curP, *bsP, *boP;
    int2 *edP;
    cudaGetSymbolAddress((void**)&hP, g_h);
    cudaGetSymbolAddress((void**)&aP, g_agg);
    cudaGetSymbolAddress((void**)&pP, g_part);
    cudaGetSymbolAddress((void**)&wp0, g_wfp0);
    cudaGetSymbolAddress((void**)&w10, g_wf10);
    cudaGetSymbolAddress((void**)&w20, g_wf20);
    cudaGetSymbolAddress((void**)&wp1, g_wfp1);
    cudaGetSymbolAddress((void**)&w11, g_wf11);
    cudaGetSymbolAddress((void**)&w21, g_wf21);
    cudaGetSymbolAddress((void**)&cntP, g_cnt);
    cudaGetSymbolAddress((void**)&rpP, g_rowptr);
    cudaGetSymbolAddress((void**)&curP, g_cursor);
    cudaGetSymbolAddress((void**)&bsP, g_bsum);
    cudaGetSymbolAddress((void**)&boP, g_boff);
    cudaGetSymbolAddress((void**)&edP, g_edata);

    const int POOL_SMEM = (8192 * 2 + 64) * 4;       // 65,792 B
    const int FCH_SMEM  = (8192 * 2) * 4;            // 65,536 B
    const int FCG_SMEM  = 8192 * 4;                  // 32,768 B
    const int FUSE_SMEM = (8192 * 3 + 64) * 4;       // 98,560 B
    cudaFuncSetAttribute(pool_gemm, cudaFuncAttributeMaxDynamicSharedMemorySize, POOL_SMEM);
    cudaFuncSetAttribute((const void*)fc_h<128>, cudaFuncAttributeMaxDynamicSharedMemorySize, FCH_SMEM);
    cudaFuncSetAttribute((const void*)fc_h<64>,  cudaFuncAttributeMaxDynamicSharedMemorySize, FCH_SMEM);
    cudaFuncSetAttribute((const void*)fc_g<64, false>, cudaFuncAttributeMaxDynamicSharedMemorySize, FCG_SMEM);
    cudaFuncSetAttribute(fcg_pool, cudaFuncAttributeMaxDynamicSharedMemorySize, FUSE_SMEM);

    int mb = (n + 63) / 64;
    int gb = (n * 32 + 255) / 256;
    int nb = (n + SCAN_CH - 1) / SCAN_CH;

    cudaStream_t s2;
    cudaStreamCreate(&s2);
    cudaEvent_t evFork, evPool0, evSp0, evK2, evSp1;
    cudaEventCreateWithFlags(&evFork, cudaEventDisableTiming);
    cudaEventCreateWithFlags(&evPool0, cudaEventDisableTiming);
    cudaEventCreateWithFlags(&evSp0, cudaEventDisableTiming);
    cudaEventCreateWithFlags(&evK2, cudaEventDisableTiming);
    cudaEventCreateWithFlags(&evSp1, cudaEventDisableTiming);

    cudaEventRecord(evFork, 0);
    cudaStreamWaitEvent(s2, evFork, 0);

    // ---- side stream: CSR build ----
    zero_cnt<<<(n + 255) / 256, 256, 0, s2>>>(cntP, n);
    hist_kernel<<<512, 512, 0, s2>>>(edst, cntP, E);
    scan_reduce<<<nb, 256, 0, s2>>>(cntP, bsP, n);
    scan_blocks<<<1, 64, 0, s2>>>(bsP, boP, rpP, nb, n);
    scan_final<<<nb, 256, 0, s2>>>(cntP, boP, rpP, curP, n);
    scatter_kernel<<<512, 512, 0, s2>>>(esrc, edst, eval_, curP, edP, E);

    // ---- main: weight splits + layer-0 pool ----
    split_w6<<<dim3(32, 6), 256>>>(pw0, f1w0, f2w0, pw1, f1w1, f2w1,
                                   wp0, w10, w20, wp1, w11, w21);
    pool_gemm<<<mb, 256, POOL_SMEM>>>(x, wp0, pb0, hP, n);
    cudaEventRecord(evPool0, 0);

    // ---- layer 0: spmm (side) || fc_h (main) ----
    cudaStreamWaitEvent(s2, evPool0, 0);
    spmm_gather<<<gb, 256, 0, s2>>>(edP, rpP, hP, aP, n);
    cudaEventRecord(evSp0, s2);

    fc_h<128><<<mb, 256, FCH_SMEM>>>(hP, w10, pP, n);

    // ---- fused fc_g(layer0) + pool(layer1) ----
    cudaStreamWaitEvent(0, evSp0, 0);
    fcg_pool<<<mb, 256, FUSE_SMEM>>>(aP, w20, f1b0, f2b0, pP, wp1, pb1, hP, n);
    cudaEventRecord(evK2, 0);

    // ---- layer 1: spmm (side) || fc_h (main), then fc_g ----
    cudaStreamWaitEvent(s2, evK2, 0);
    spmm_gather<<<gb, 256, 0, s2>>>(edP, rpP, hP, aP, n);
    cudaEventRecord(evSp1, s2);

    fc_h<64><<<mb, 256, FCH_SMEM>>>(hP, w11, out, n);
    cudaStreamWaitEvent(0, evSp1, 0);
    fc_g<64, false><<<mb, 256, FCG_SMEM>>>(aP, w21, f1b1, f2b1, out, n);
}